// round 2
// baseline (speedup 1.0000x reference)
#include <cuda_runtime.h>
#include <cuda_bf16.h>
#include <math.h>

// Problem dims (fixed by reference)
#define NB 4
#define SEQ 2048
#define EMB 1024
#define NH 16
#define HD 64
#define FF 4096
#define MROWS (NB * SEQ)          // 8192
#define X_SIZE (NB * SEQ * EMB)   // 8388608

// ---------------- scratch (device globals; no allocation allowed) ----------
__device__ float g_xn [MROWS * EMB];
__device__ float g_q  [MROWS * EMB];
__device__ float g_k  [MROWS * EMB];
__device__ float g_v  [MROWS * EMB];
__device__ float g_att[MROWS * EMB];
__device__ float g_x1 [MROWS * EMB];
__device__ float g_xn2[MROWS * EMB];
__device__ float g_ffn[MROWS * FF];

// ---------------- layernorm: one block per row of 1024 ---------------------
__global__ __launch_bounds__(256) void ln_kernel(
    const float* __restrict__ in, const float* __restrict__ g,
    const float* __restrict__ b, float* __restrict__ out)
{
    const int row = blockIdx.x;
    const float* xr = in + (size_t)row * EMB;
    float* orow = out + (size_t)row * EMB;
    const int tid = threadIdx.x;

    float vals[4];
    float s = 0.f, sq = 0.f;
#pragma unroll
    for (int i = 0; i < 4; i++) {
        float v = xr[i * 256 + tid];
        vals[i] = v; s += v; sq += v * v;
    }
    // block reduce (sum, sumsq)
    __shared__ float red[16];
#pragma unroll
    for (int off = 16; off; off >>= 1) {
        s  += __shfl_xor_sync(0xffffffffu, s,  off);
        sq += __shfl_xor_sync(0xffffffffu, sq, off);
    }
    const int warp = tid >> 5, lane = tid & 31;
    if (lane == 0) { red[warp] = s; red[warp + 8] = sq; }
    __syncthreads();
    if (warp == 0) {
        float ss = (lane < 8) ? red[lane] : 0.f;
        float qq = (lane < 8) ? red[lane + 8] : 0.f;
#pragma unroll
        for (int off = 4; off; off >>= 1) {
            ss += __shfl_xor_sync(0xffffffffu, ss, off);
            qq += __shfl_xor_sync(0xffffffffu, qq, off);
        }
        if (lane == 0) { red[0] = ss; red[1] = qq; }
    }
    __syncthreads();
    const float mean = red[0] * (1.0f / EMB);
    const float var  = red[1] * (1.0f / EMB) - mean * mean;
    const float inv  = rsqrtf(var + 1e-5f);
#pragma unroll
    for (int i = 0; i < 4; i++) {
        int idx = i * 256 + tid;
        orow[idx] = (vals[i] - mean) * inv * g[idx] + b[idx];
    }
}

// ---------------- SGEMM: C = act(A@B + bias [+ res]) -----------------------
// A [M,K] rm, B [K,N] rm, bias [N], res [M,N], C [M,N].
// 128x128 tile, BK=8, 256 threads, 8x8 per thread.
template <bool RELU, bool RES>
__global__ __launch_bounds__(256) void gemm_kernel(
    const float* __restrict__ A, const float* __restrict__ B,
    const float* __restrict__ bias, const float* __restrict__ res,
    float* __restrict__ C, int M, int N, int K)
{
    __shared__ float As[8][128];
    __shared__ float Bs[8][128];

    const int tid = threadIdx.x;
    const int ty = tid >> 4, tx = tid & 15;
    const int rowStart = blockIdx.y * 128;
    const int colStart = blockIdx.x * 128;

    const int aRow = tid >> 1, aCol = (tid & 1) * 4;
    const int bRow = tid >> 5, bCol = (tid & 31) * 4;

    float acc[8][8];
#pragma unroll
    for (int i = 0; i < 8; i++)
#pragma unroll
        for (int j = 0; j < 8; j++) acc[i][j] = 0.f;

    for (int k0 = 0; k0 < K; k0 += 8) {
        float4 av = *reinterpret_cast<const float4*>(
            &A[(size_t)(rowStart + aRow) * K + k0 + aCol]);
        As[aCol + 0][aRow] = av.x;
        As[aCol + 1][aRow] = av.y;
        As[aCol + 2][aRow] = av.z;
        As[aCol + 3][aRow] = av.w;
        float4 bv = *reinterpret_cast<const float4*>(
            &B[(size_t)(k0 + bRow) * N + colStart + bCol]);
        *reinterpret_cast<float4*>(&Bs[bRow][bCol]) = bv;
        __syncthreads();

#pragma unroll
        for (int k = 0; k < 8; k++) {
            float4 a0 = *reinterpret_cast<const float4*>(&As[k][ty * 8]);
            float4 a1 = *reinterpret_cast<const float4*>(&As[k][ty * 8 + 4]);
            float4 b0 = *reinterpret_cast<const float4*>(&Bs[k][tx * 8]);
            float4 b1 = *reinterpret_cast<const float4*>(&Bs[k][tx * 8 + 4]);
            float a[8] = {a0.x, a0.y, a0.z, a0.w, a1.x, a1.y, a1.z, a1.w};
            float b[8] = {b0.x, b0.y, b0.z, b0.w, b1.x, b1.y, b1.z, b1.w};
#pragma unroll
            for (int i = 0; i < 8; i++)
#pragma unroll
                for (int j = 0; j < 8; j++)
                    acc[i][j] = fmaf(a[i], b[j], acc[i][j]);
        }
        __syncthreads();
    }

#pragma unroll
    for (int i = 0; i < 8; i++) {
        const int row = rowStart + ty * 8 + i;
#pragma unroll
        for (int j = 0; j < 8; j++) {
            const int col = colStart + tx * 8 + j;
            float r = acc[i][j] + bias[col];
            if (RES) r += res[(size_t)row * N + col];
            if (RELU) r = fmaxf(r, 0.f);
            C[(size_t)row * N + col] = r;
        }
    }
}

// ---------------- flash attention (fp32) ------------------------------------
// q,k,v,out: [NB, SEQ, EMB] with head h occupying cols h*64..h*64+63.
// grid: (SEQ/64, NH, NB); 256 threads; Q-tile 64, K-tile 32.
__global__ __launch_bounds__(256) void attn_kernel(
    const float* __restrict__ q, const float* __restrict__ k,
    const float* __restrict__ v, float* __restrict__ out)
{
    __shared__ float Qs[64][HD + 1];
    __shared__ float Ks[32][HD + 1];
    __shared__ float Vs[32][HD + 1];
    __shared__ float Ps[64][33];

    const int qt = blockIdx.x, h = blockIdx.y, n = blockIdx.z;
    const int tid = threadIdx.x;
    const int r = tid >> 2;      // query row within tile (0..63)
    const int c4 = tid & 3;      // quarter index
    const float scale = 0.125f;  // 1/sqrt(64)

    const size_t base = ((size_t)n * SEQ) * EMB + h * HD;

    for (int i = tid; i < 64 * HD; i += 256) {
        int rr = i >> 6, d = i & 63;
        Qs[rr][d] = q[base + (size_t)(qt * 64 + rr) * EMB + d] * scale;
    }

    float m = -INFINITY, l = 0.f;
    float o[16];
#pragma unroll
    for (int i = 0; i < 16; i++) o[i] = 0.f;
    const int d0 = c4 * 16;
    const int c0 = c4 * 8;

    for (int kt = 0; kt < SEQ / 32; kt++) {
        __syncthreads();  // previous iter done reading Ks/Vs/Ps
        for (int i = tid; i < 32 * HD; i += 256) {
            int rr = i >> 6, d = i & 63;
            size_t gi = base + (size_t)(kt * 32 + rr) * EMB + d;
            Ks[rr][d] = k[gi];
            Vs[rr][d] = v[gi];
        }
        __syncthreads();

        float s[8];
#pragma unroll
        for (int j = 0; j < 8; j++) s[j] = 0.f;
        for (int d = 0; d < HD; d++) {
            float qv = Qs[r][d];
#pragma unroll
            for (int j = 0; j < 8; j++)
                s[j] = fmaf(qv, Ks[c0 + j][d], s[j]);
        }
        float mt = s[0];
#pragma unroll
        for (int j = 1; j < 8; j++) mt = fmaxf(mt, s[j]);
        mt = fmaxf(mt, __shfl_xor_sync(0xffffffffu, mt, 1));
        mt = fmaxf(mt, __shfl_xor_sync(0xffffffffu, mt, 2));

        const float mn = fmaxf(m, mt);
        const float corr = __expf(m - mn);
        float ls = 0.f;
#pragma unroll
        for (int j = 0; j < 8; j++) {
            float p = __expf(s[j] - mn);
            Ps[r][c0 + j] = p;
            ls += p;
        }
        ls += __shfl_xor_sync(0xffffffffu, ls, 1);
        ls += __shfl_xor_sync(0xffffffffu, ls, 2);
        l = l * corr + ls;
        m = mn;
#pragma unroll
        for (int i = 0; i < 16; i++) o[i] *= corr;
        __syncthreads();  // Ps visible to whole row

        for (int j = 0; j < 32; j++) {
            float pv = Ps[r][j];
#pragma unroll
            for (int dd = 0; dd < 16; dd++)
                o[dd] = fmaf(pv, Vs[j][d0 + dd], o[dd]);
        }
    }

    const float invl = 1.f / l;
    const size_t ob = base + (size_t)(qt * 64 + r) * EMB + d0;
#pragma unroll
    for (int dd = 0; dd < 16; dd++) out[ob + dd] = o[dd] * invl;
}

// ---------------- logits + GAN loss -----------------------------------------
__global__ void loss_kernel(const float* __restrict__ xfin,
                            const float* __restrict__ wlr,
                            const float* __restrict__ blr,
                            float* __restrict__ out)  // out -> d_out + X_SIZE
{
    __shared__ float slog[4];
    const int warp = threadIdx.x >> 5, lane = threadIdx.x & 31;
    if (warp < 4) {
        const float* xr = xfin + (size_t)warp * SEQ * EMB;  // token 0
        float s = 0.f;
        for (int i = lane; i < EMB; i += 32) s = fmaf(xr[i], wlr[i], s);
#pragma unroll
        for (int off = 16; off; off >>= 1)
            s += __shfl_xor_sync(0xffffffffu, s, off);
        if (lane == 0) slog[warp] = s + blr[0];
    }
    __syncthreads();
    if (threadIdx.x == 0) {
        auto sp = [](float t) {
            return fmaxf(t, 0.f) + log1pf(expf(-fabsf(t)));
        };
        float loss_real = 0.5f * (sp(-slog[0]) + sp(-slog[1]));
        float loss_fake = 0.5f * (sp( slog[2]) + sp( slog[3]));
        out[0] = 0.5f * (loss_fake + loss_real);
        out[1] = loss_fake;
    }
}

// ---------------- launch ----------------------------------------------------
extern "C" void kernel_launch(void* const* d_in, const int* in_sizes, int n_in,
                              void* d_out, int out_size)
{
    const float* x     = (const float*)d_in[0];
    const float* wq    = (const float*)d_in[1];
    const float* bq    = (const float*)d_in[2];
    const float* wk    = (const float*)d_in[3];
    const float* bk    = (const float*)d_in[4];
    const float* wv    = (const float*)d_in[5];
    const float* bv    = (const float*)d_in[6];
    const float* wo    = (const float*)d_in[7];
    const float* bo    = (const float*)d_in[8];
    const float* ln1_g = (const float*)d_in[9];
    const float* ln1_b = (const float*)d_in[10];
    const float* ln2_g = (const float*)d_in[11];
    const float* ln2_b = (const float*)d_in[12];
    const float* w1    = (const float*)d_in[13];
    const float* b1    = (const float*)d_in[14];
    const float* w2    = (const float*)d_in[15];
    const float* b2    = (const float*)d_in[16];
    const float* wlr   = (const float*)d_in[17];
    const float* blr   = (const float*)d_in[18];
    float* out = (float*)d_out;

    float *xn, *q, *k, *v, *att, *x1, *xn2, *ffn;
    cudaGetSymbolAddress((void**)&xn,  g_xn);
    cudaGetSymbolAddress((void**)&q,   g_q);
    cudaGetSymbolAddress((void**)&k,   g_k);
    cudaGetSymbolAddress((void**)&v,   g_v);
    cudaGetSymbolAddress((void**)&att, g_att);
    cudaGetSymbolAddress((void**)&x1,  g_x1);
    cudaGetSymbolAddress((void**)&xn2, g_xn2);
    cudaGetSymbolAddress((void**)&ffn, g_ffn);

    // 1) LN1
    ln_kernel<<<MROWS, 256>>>(x, ln1_g, ln1_b, xn);

    // 2) Q,K,V projections
    dim3 gProj(EMB / 128, MROWS / 128);
    gemm_kernel<false, false><<<gProj, 256>>>(xn, wq, bq, nullptr, q, MROWS, EMB, EMB);
    gemm_kernel<false, false><<<gProj, 256>>>(xn, wk, bk, nullptr, k, MROWS, EMB, EMB);
    gemm_kernel<false, false><<<gProj, 256>>>(xn, wv, bv, nullptr, v, MROWS, EMB, EMB);

    // 3) attention
    dim3 gAttn(SEQ / 64, NH, NB);
    attn_kernel<<<gAttn, 256>>>(q, k, v, att);

    // 4) out-proj + residual -> x1
    gemm_kernel<false, true><<<gProj, 256>>>(att, wo, bo, x, x1, MROWS, EMB, EMB);

    // 5) LN2
    ln_kernel<<<MROWS, 256>>>(x1, ln2_g, ln2_b, xn2);

    // 6) FFN1 with ReLU
    dim3 gFF1(FF / 128, MROWS / 128);
    gemm_kernel<true, false><<<gFF1, 256>>>(xn2, w1, b1, nullptr, ffn, MROWS, FF, EMB);

    // 7) FFN2 + residual -> final x (directly into d_out)
    gemm_kernel<false, true><<<gProj, 256>>>(ffn, w2, b2, x1, out, MROWS, EMB, FF);

    // 8) logits + losses
    loss_kernel<<<1, 128>>>(out, wlr, blr, out + X_SIZE);
}

// round 3
// speedup vs baseline: 1.7826x; 1.7826x over previous
#include <cuda_runtime.h>
#include <cuda_bf16.h>
#include <math.h>

// Problem dims (fixed by reference)
#define NB 4
#define SEQ 2048
#define EMB 1024
#define NH 16
#define HD 64
#define FF 4096
#define MROWS (NB * SEQ)          // 8192
#define X_SIZE (NB * SEQ * EMB)   // 8388608

// ---------------- scratch (device globals; no allocation allowed) ----------
__device__ float g_xn [MROWS * EMB];
__device__ float g_q  [MROWS * EMB];
__device__ float g_k  [MROWS * EMB];
__device__ float g_v  [MROWS * EMB];
__device__ float g_att[MROWS * EMB];
__device__ float g_x1 [MROWS * EMB];
__device__ float g_xn2[MROWS * EMB];
__device__ float g_ffn[MROWS * FF];

// ---------------- layernorm: one block per row of 1024 ---------------------
__global__ __launch_bounds__(256) void ln_kernel(
    const float* __restrict__ in, const float* __restrict__ g,
    const float* __restrict__ b, float* __restrict__ out)
{
    const int row = blockIdx.x;
    const float* xr = in + (size_t)row * EMB;
    float* orow = out + (size_t)row * EMB;
    const int tid = threadIdx.x;

    float vals[4];
    float s = 0.f, sq = 0.f;
#pragma unroll
    for (int i = 0; i < 4; i++) {
        float v = xr[i * 256 + tid];
        vals[i] = v; s += v; sq += v * v;
    }
    __shared__ float red[16];
#pragma unroll
    for (int off = 16; off; off >>= 1) {
        s  += __shfl_xor_sync(0xffffffffu, s,  off);
        sq += __shfl_xor_sync(0xffffffffu, sq, off);
    }
    const int warp = tid >> 5, lane = tid & 31;
    if (lane == 0) { red[warp] = s; red[warp + 8] = sq; }
    __syncthreads();
    if (warp == 0) {
        float ss = (lane < 8) ? red[lane] : 0.f;
        float qq = (lane < 8) ? red[lane + 8] : 0.f;
#pragma unroll
        for (int off = 4; off; off >>= 1) {
            ss += __shfl_xor_sync(0xffffffffu, ss, off);
            qq += __shfl_xor_sync(0xffffffffu, qq, off);
        }
        if (lane == 0) { red[0] = ss; red[1] = qq; }
    }
    __syncthreads();
    const float mean = red[0] * (1.0f / EMB);
    const float var  = red[1] * (1.0f / EMB) - mean * mean;
    const float inv  = rsqrtf(var + 1e-5f);
#pragma unroll
    for (int i = 0; i < 4; i++) {
        int idx = i * 256 + tid;
        orow[idx] = (vals[i] - mean) * inv * g[idx] + b[idx];
    }
}

// ---------------- SGEMM: C = act(A@B + bias [+ res]) -----------------------
// Double-buffered smem, prefetch LDG before compute, one sync per k-step.
template <bool RELU, bool RES>
__global__ __launch_bounds__(256, 2) void gemm_kernel(
    const float* __restrict__ A, const float* __restrict__ B,
    const float* __restrict__ bias, const float* __restrict__ res,
    float* __restrict__ C, int M, int N, int K)
{
    __shared__ float As[2][8][128];
    __shared__ float Bs[2][8][128];

    const int tid = threadIdx.x;
    const int ty = tid >> 4, tx = tid & 15;
    const int rowStart = blockIdx.y * 128;
    const int colStart = blockIdx.x * 128;

    const int aRow = tid >> 1, aCol = (tid & 1) * 4;
    const int bRow = tid >> 5, bCol = (tid & 31) * 4;

    const float* Aptr = A + (size_t)(rowStart + aRow) * K + aCol;
    const float* Bptr = B + (size_t)bRow * N + colStart + bCol;

    float acc[8][8];
#pragma unroll
    for (int i = 0; i < 8; i++)
#pragma unroll
        for (int j = 0; j < 8; j++) acc[i][j] = 0.f;

    // prologue: tile 0 into buf 0
    {
        float4 av = *reinterpret_cast<const float4*>(Aptr);
        float4 bv = *reinterpret_cast<const float4*>(Bptr);
        As[0][aCol + 0][aRow] = av.x;
        As[0][aCol + 1][aRow] = av.y;
        As[0][aCol + 2][aRow] = av.z;
        As[0][aCol + 3][aRow] = av.w;
        *reinterpret_cast<float4*>(&Bs[0][bRow][bCol]) = bv;
    }
    __syncthreads();

    int buf = 0;
    for (int k0 = 8; k0 <= K; k0 += 8) {
        float4 av, bv;
        const bool more = (k0 < K);
        if (more) {
            av = *reinterpret_cast<const float4*>(Aptr + k0);
            bv = *reinterpret_cast<const float4*>(Bptr + (size_t)k0 * N);
        }
#pragma unroll
        for (int kk = 0; kk < 8; kk++) {
            float4 a0 = *reinterpret_cast<const float4*>(&As[buf][kk][ty * 8]);
            float4 a1 = *reinterpret_cast<const float4*>(&As[buf][kk][ty * 8 + 4]);
            float4 b0 = *reinterpret_cast<const float4*>(&Bs[buf][kk][tx * 8]);
            float4 b1 = *reinterpret_cast<const float4*>(&Bs[buf][kk][tx * 8 + 4]);
            float a[8] = {a0.x, a0.y, a0.z, a0.w, a1.x, a1.y, a1.z, a1.w};
            float b[8] = {b0.x, b0.y, b0.z, b0.w, b1.x, b1.y, b1.z, b1.w};
#pragma unroll
            for (int i = 0; i < 8; i++)
#pragma unroll
                for (int j = 0; j < 8; j++)
                    acc[i][j] = fmaf(a[i], b[j], acc[i][j]);
        }
        if (more) {
            const int nb = buf ^ 1;
            As[nb][aCol + 0][aRow] = av.x;
            As[nb][aCol + 1][aRow] = av.y;
            As[nb][aCol + 2][aRow] = av.z;
            As[nb][aCol + 3][aRow] = av.w;
            *reinterpret_cast<float4*>(&Bs[nb][bRow][bCol]) = bv;
            __syncthreads();
            buf = nb;
        }
    }

    // epilogue: float4 stores
    float4 bs0 = *reinterpret_cast<const float4*>(&bias[colStart + tx * 8]);
    float4 bs1 = *reinterpret_cast<const float4*>(&bias[colStart + tx * 8 + 4]);
#pragma unroll
    for (int i = 0; i < 8; i++) {
        const int row = rowStart + ty * 8 + i;
        const size_t off = (size_t)row * N + colStart + tx * 8;
        float4 r0 = make_float4(acc[i][0] + bs0.x, acc[i][1] + bs0.y,
                                acc[i][2] + bs0.z, acc[i][3] + bs0.w);
        float4 r1 = make_float4(acc[i][4] + bs1.x, acc[i][5] + bs1.y,
                                acc[i][6] + bs1.z, acc[i][7] + bs1.w);
        if (RES) {
            float4 q0 = *reinterpret_cast<const float4*>(&res[off]);
            float4 q1 = *reinterpret_cast<const float4*>(&res[off + 4]);
            r0.x += q0.x; r0.y += q0.y; r0.z += q0.z; r0.w += q0.w;
            r1.x += q1.x; r1.y += q1.y; r1.z += q1.z; r1.w += q1.w;
        }
        if (RELU) {
            r0.x = fmaxf(r0.x, 0.f); r0.y = fmaxf(r0.y, 0.f);
            r0.z = fmaxf(r0.z, 0.f); r0.w = fmaxf(r0.w, 0.f);
            r1.x = fmaxf(r1.x, 0.f); r1.y = fmaxf(r1.y, 0.f);
            r1.z = fmaxf(r1.z, 0.f); r1.w = fmaxf(r1.w, 0.f);
        }
        *reinterpret_cast<float4*>(&C[off]) = r0;
        *reinterpret_cast<float4*>(&C[off + 4]) = r1;
    }
}

// ---------------- flash attention (fp32, register-tiled) -------------------
// q,k,v,out: [NB, SEQ, EMB], head h at cols h*64..h*64+63.
// grid: (SEQ/64, NH, NB); 256 threads. 64x64 Q-tile x 64 K-tile.
// Thread (ty,tx) owns rows ty*4..+3 and cols/dims tx*4..+3 (4x4 register tile).
// K and V share one swizzled smem buffer: float4 slot = d4 ^ (token>>2).
__global__ __launch_bounds__(256) void attn_kernel(
    const float* __restrict__ q, const float* __restrict__ k,
    const float* __restrict__ v, float* __restrict__ out)
{
    __shared__ float Qs[64][64];   // pre-scaled Q tile
    __shared__ float KV[64][64];   // swizzled K tile, then V tile
    __shared__ float Ps[64][64];   // probabilities

    const int qt = blockIdx.x, h = blockIdx.y, n = blockIdx.z;
    const int tid = threadIdx.x;
    const int ty = tid >> 4, tx = tid & 15;
    const int r0 = ty * 4, c0 = tx * 4;
    const size_t base = ((size_t)n * SEQ) * EMB + h * HD;

    // load + scale Q tile (coalesced float4)
    {
        int u = tid;
#pragma unroll
        for (int it = 0; it < 4; it++, u += 256) {
            const int rr = u >> 4, d4 = u & 15;
            float4 t = *reinterpret_cast<const float4*>(
                &q[base + (size_t)(qt * 64 + rr) * EMB + d4 * 4]);
            t.x *= 0.125f; t.y *= 0.125f; t.z *= 0.125f; t.w *= 0.125f;
            *reinterpret_cast<float4*>(&Qs[rr][d4 * 4]) = t;
        }
    }

    float m[4], l[4], o[4][4];
#pragma unroll
    for (int i = 0; i < 4; i++) {
        m[i] = -INFINITY; l[i] = 0.f;
#pragma unroll
        for (int j = 0; j < 4; j++) o[i][j] = 0.f;
    }

    for (int kt = 0; kt < SEQ / 64; kt++) {
        __syncthreads();   // prev PV done with KV(V) / Ps; Q load done (it=0)
        // ---- load K tile (swizzled) ----
        {
            int u = tid;
#pragma unroll
            for (int it = 0; it < 4; it++, u += 256) {
                const int cc = u >> 4, d4 = u & 15;
                float4 t = *reinterpret_cast<const float4*>(
                    &k[base + (size_t)(kt * 64 + cc) * EMB + d4 * 4]);
                *reinterpret_cast<float4*>(&KV[cc][(d4 ^ (cc >> 2)) * 4]) = t;
            }
        }
        __syncthreads();

        // ---- S = Q K^T (4x4 per thread) ----
        float s[4][4];
#pragma unroll
        for (int i = 0; i < 4; i++)
#pragma unroll
            for (int j = 0; j < 4; j++) s[i][j] = 0.f;

#pragma unroll
        for (int d4 = 0; d4 < 16; d4++) {
            float4 kf[4];
#pragma unroll
            for (int j = 0; j < 4; j++) {
                const int cc = c0 + j;
                kf[j] = *reinterpret_cast<const float4*>(
                    &KV[cc][(d4 ^ (cc >> 2)) * 4]);
            }
#pragma unroll
            for (int i = 0; i < 4; i++) {
                float4 qf = *reinterpret_cast<const float4*>(&Qs[r0 + i][d4 * 4]);
#pragma unroll
                for (int j = 0; j < 4; j++) {
                    s[i][j] = fmaf(qf.x, kf[j].x, s[i][j]);
                    s[i][j] = fmaf(qf.y, kf[j].y, s[i][j]);
                    s[i][j] = fmaf(qf.z, kf[j].z, s[i][j]);
                    s[i][j] = fmaf(qf.w, kf[j].w, s[i][j]);
                }
            }
        }

        // ---- online softmax (stats fully in registers; rows are thread-resident) ----
#pragma unroll
        for (int i = 0; i < 4; i++) {
            float mt = fmaxf(fmaxf(s[i][0], s[i][1]), fmaxf(s[i][2], s[i][3]));
            mt = fmaxf(mt, __shfl_xor_sync(0xffffffffu, mt, 1));
            mt = fmaxf(mt, __shfl_xor_sync(0xffffffffu, mt, 2));
            mt = fmaxf(mt, __shfl_xor_sync(0xffffffffu, mt, 4));
            mt = fmaxf(mt, __shfl_xor_sync(0xffffffffu, mt, 8));
            const float mn = fmaxf(m[i], mt);
            const float corr = __expf(m[i] - mn);
            float ls = 0.f;
#pragma unroll
            for (int j = 0; j < 4; j++) {
                const float p = __expf(s[i][j] - mn);
                s[i][j] = p; ls += p;
            }
            ls += __shfl_xor_sync(0xffffffffu, ls, 1);
            ls += __shfl_xor_sync(0xffffffffu, ls, 2);
            ls += __shfl_xor_sync(0xffffffffu, ls, 4);
            ls += __shfl_xor_sync(0xffffffffu, ls, 8);
            l[i] = l[i] * corr + ls;
            m[i] = mn;
#pragma unroll
            for (int j = 0; j < 4; j++) o[i][j] *= corr;
            *reinterpret_cast<float4*>(&Ps[r0 + i][c0]) =
                make_float4(s[i][0], s[i][1], s[i][2], s[i][3]);
        }
        __syncthreads();   // S done reading K, Ps complete

        // ---- load V tile into the same buffer (swizzled) ----
        {
            int u = tid;
#pragma unroll
            for (int it = 0; it < 4; it++, u += 256) {
                const int cc = u >> 4, d4 = u & 15;
                float4 t = *reinterpret_cast<const float4*>(
                    &v[base + (size_t)(kt * 64 + cc) * EMB + d4 * 4]);
                *reinterpret_cast<float4*>(&KV[cc][(d4 ^ (cc >> 2)) * 4]) = t;
            }
        }
        __syncthreads();

        // ---- O += P V (4 rows x 4 dims per thread) ----
#pragma unroll
        for (int j4 = 0; j4 < 16; j4++) {
            float4 vf[4];
#pragma unroll
            for (int t = 0; t < 4; t++) {
                const int cc = j4 * 4 + t;
                vf[t] = *reinterpret_cast<const float4*>(
                    &KV[cc][(tx ^ (cc >> 2)) * 4]);
            }
#pragma unroll
            for (int i = 0; i < 4; i++) {
                float4 pf = *reinterpret_cast<const float4*>(&Ps[r0 + i][j4 * 4]);
                o[i][0] = fmaf(pf.x, vf[0].x, o[i][0]);
                o[i][1] = fmaf(pf.x, vf[0].y, o[i][1]);
                o[i][2] = fmaf(pf.x, vf[0].z, o[i][2]);
                o[i][3] = fmaf(pf.x, vf[0].w, o[i][3]);
                o[i][0] = fmaf(pf.y, vf[1].x, o[i][0]);
                o[i][1] = fmaf(pf.y, vf[1].y, o[i][1]);
                o[i][2] = fmaf(pf.y, vf[1].z, o[i][2]);
                o[i][3] = fmaf(pf.y, vf[1].w, o[i][3]);
                o[i][0] = fmaf(pf.z, vf[2].x, o[i][0]);
                o[i][1] = fmaf(pf.z, vf[2].y, o[i][1]);
                o[i][2] = fmaf(pf.z, vf[2].z, o[i][2]);
                o[i][3] = fmaf(pf.z, vf[2].w, o[i][3]);
                o[i][0] = fmaf(pf.w, vf[3].x, o[i][0]);
                o[i][1] = fmaf(pf.w, vf[3].y, o[i][1]);
                o[i][2] = fmaf(pf.w, vf[3].z, o[i][2]);
                o[i][3] = fmaf(pf.w, vf[3].w, o[i][3]);
            }
        }
    }

    // ---- write O / l ----
#pragma unroll
    for (int i = 0; i < 4; i++) {
        const float inv = 1.f / l[i];
        float4 t = make_float4(o[i][0] * inv, o[i][1] * inv,
                               o[i][2] * inv, o[i][3] * inv);
        *reinterpret_cast<float4*>(
            &out[base + (size_t)(qt * 64 + r0 + i) * EMB + c0]) = t;
    }
}

// ---------------- logits + GAN loss -----------------------------------------
__global__ void loss_kernel(const float* __restrict__ xfin,
                            const float* __restrict__ wlr,
                            const float* __restrict__ blr,
                            float* __restrict__ out)
{
    __shared__ float slog[4];
    const int warp = threadIdx.x >> 5, lane = threadIdx.x & 31;
    if (warp < 4) {
        const float* xr = xfin + (size_t)warp * SEQ * EMB;  // token 0
        float s = 0.f;
        for (int i = lane; i < EMB; i += 32) s = fmaf(xr[i], wlr[i], s);
#pragma unroll
        for (int off = 16; off; off >>= 1)
            s += __shfl_xor_sync(0xffffffffu, s, off);
        if (lane == 0) slog[warp] = s + blr[0];
    }
    __syncthreads();
    if (threadIdx.x == 0) {
        auto sp = [](float t) {
            return fmaxf(t, 0.f) + log1pf(expf(-fabsf(t)));
        };
        float loss_real = 0.5f * (sp(-slog[0]) + sp(-slog[1]));
        float loss_fake = 0.5f * (sp( slog[2]) + sp( slog[3]));
        out[0] = 0.5f * (loss_fake + loss_real);
        out[1] = loss_fake;
    }
}

// ---------------- launch ----------------------------------------------------
extern "C" void kernel_launch(void* const* d_in, const int* in_sizes, int n_in,
                              void* d_out, int out_size)
{
    const float* x     = (const float*)d_in[0];
    const float* wq    = (const float*)d_in[1];
    const float* bq    = (const float*)d_in[2];
    const float* wk    = (const float*)d_in[3];
    const float* bk    = (const float*)d_in[4];
    const float* wv    = (const float*)d_in[5];
    const float* bv    = (const float*)d_in[6];
    const float* wo    = (const float*)d_in[7];
    const float* bo    = (const float*)d_in[8];
    const float* ln1_g = (const float*)d_in[9];
    const float* ln1_b = (const float*)d_in[10];
    const float* ln2_g = (const float*)d_in[11];
    const float* ln2_b = (const float*)d_in[12];
    const float* w1    = (const float*)d_in[13];
    const float* b1    = (const float*)d_in[14];
    const float* w2    = (const float*)d_in[15];
    const float* b2    = (const float*)d_in[16];
    const float* wlr   = (const float*)d_in[17];
    const float* blr   = (const float*)d_in[18];
    float* out = (float*)d_out;

    float *xn, *q, *k, *v, *att, *x1, *xn2, *ffn;
    cudaGetSymbolAddress((void**)&xn,  g_xn);
    cudaGetSymbolAddress((void**)&q,   g_q);
    cudaGetSymbolAddress((void**)&k,   g_k);
    cudaGetSymbolAddress((void**)&v,   g_v);
    cudaGetSymbolAddress((void**)&att, g_att);
    cudaGetSymbolAddress((void**)&x1,  g_x1);
    cudaGetSymbolAddress((void**)&xn2, g_xn2);
    cudaGetSymbolAddress((void**)&ffn, g_ffn);

    // 1) LN1
    ln_kernel<<<MROWS, 256>>>(x, ln1_g, ln1_b, xn);

    // 2) Q,K,V projections
    dim3 gProj(EMB / 128, MROWS / 128);
    gemm_kernel<false, false><<<gProj, 256>>>(xn, wq, bq, nullptr, q, MROWS, EMB, EMB);
    gemm_kernel<false, false><<<gProj, 256>>>(xn, wk, bk, nullptr, k, MROWS, EMB, EMB);
    gemm_kernel<false, false><<<gProj, 256>>>(xn, wv, bv, nullptr, v, MROWS, EMB, EMB);

    // 3) attention
    dim3 gAttn(SEQ / 64, NH, NB);
    attn_kernel<<<gAttn, 256>>>(q, k, v, att);

    // 4) out-proj + residual -> x1
    gemm_kernel<false, true><<<gProj, 256>>>(att, wo, bo, x, x1, MROWS, EMB, EMB);

    // 5) LN2
    ln_kernel<<<MROWS, 256>>>(x1, ln2_g, ln2_b, xn2);

    // 6) FFN1 with ReLU
    dim3 gFF1(FF / 128, MROWS / 128);
    gemm_kernel<true, false><<<gFF1, 256>>>(xn2, w1, b1, nullptr, ffn, MROWS, FF, EMB);

    // 7) FFN2 + residual -> final x (directly into d_out)
    gemm_kernel<false, true><<<gProj, 256>>>(ffn, w2, b2, x1, out, MROWS, EMB, FF);

    // 8) logits + losses
    loss_kernel<<<1, 128>>>(out, wlr, blr, out + X_SIZE);
}

// round 4
// speedup vs baseline: 3.1039x; 1.7412x over previous
#include <cuda_runtime.h>
#include <cuda_bf16.h>
#include <math.h>
#include <stdint.h>

// Problem dims (fixed by reference)
#define NB 4
#define SEQ 2048
#define EMB 1024
#define NH 16
#define HD 64
#define FF 4096
#define MROWS (NB * SEQ)          // 8192
#define X_SIZE (NB * SEQ * EMB)   // 8388608

// ---------------- scratch (device globals; no allocation allowed) ----------
__device__ float g_xn [MROWS * EMB];
__device__ float g_q  [MROWS * EMB];
__device__ float g_k  [MROWS * EMB];
__device__ float g_v  [MROWS * EMB];
__device__ float g_att[MROWS * EMB];
__device__ float g_x1 [MROWS * EMB];
__device__ float g_xn2[MROWS * EMB];
__device__ float g_ffn[MROWS * FF];

// ---------------- helpers ---------------------------------------------------
__device__ __forceinline__ float tf32r(float x) {
    uint32_t u;
    asm("cvt.rna.tf32.f32 %0, %1;" : "=r"(u) : "f"(x));
    return __uint_as_float(u);
}

__device__ __forceinline__ void mma_tf32(float d[4],
                                         uint32_t a0, uint32_t a1,
                                         uint32_t a2, uint32_t a3,
                                         uint32_t b0, uint32_t b1) {
    asm volatile(
        "mma.sync.aligned.m16n8k8.row.col.f32.tf32.tf32.f32 "
        "{%0,%1,%2,%3}, {%4,%5,%6,%7}, {%8,%9}, {%0,%1,%2,%3};"
        : "+f"(d[0]), "+f"(d[1]), "+f"(d[2]), "+f"(d[3])
        : "r"(a0), "r"(a1), "r"(a2), "r"(a3), "r"(b0), "r"(b1));
}

// ---------------- layernorm: one block per row of 1024 ---------------------
__global__ __launch_bounds__(256) void ln_kernel(
    const float* __restrict__ in, const float* __restrict__ g,
    const float* __restrict__ b, float* __restrict__ out)
{
    const int row = blockIdx.x;
    const float* xr = in + (size_t)row * EMB;
    float* orow = out + (size_t)row * EMB;
    const int tid = threadIdx.x;

    float vals[4];
    float s = 0.f, sq = 0.f;
#pragma unroll
    for (int i = 0; i < 4; i++) {
        float v = xr[i * 256 + tid];
        vals[i] = v; s += v; sq += v * v;
    }
    __shared__ float red[16];
#pragma unroll
    for (int off = 16; off; off >>= 1) {
        s  += __shfl_xor_sync(0xffffffffu, s,  off);
        sq += __shfl_xor_sync(0xffffffffu, sq, off);
    }
    const int warp = tid >> 5, lane = tid & 31;
    if (lane == 0) { red[warp] = s; red[warp + 8] = sq; }
    __syncthreads();
    if (warp == 0) {
        float ss = (lane < 8) ? red[lane] : 0.f;
        float qq = (lane < 8) ? red[lane + 8] : 0.f;
#pragma unroll
        for (int off = 4; off; off >>= 1) {
            ss += __shfl_xor_sync(0xffffffffu, ss, off);
            qq += __shfl_xor_sync(0xffffffffu, qq, off);
        }
        if (lane == 0) { red[0] = ss; red[1] = qq; }
    }
    __syncthreads();
    const float mean = red[0] * (1.0f / EMB);
    const float var  = red[1] * (1.0f / EMB) - mean * mean;
    const float inv  = rsqrtf(var + 1e-5f);
#pragma unroll
    for (int i = 0; i < 4; i++) {
        int idx = i * 256 + tid;
        orow[idx] = (vals[i] - mean) * inv * g[idx] + b[idx];
    }
}

// ---------------- tf32 tensor-core GEMM: C = act(A@B + bias [+ res]) -------
// A [M,K] rm, B [K,N] rm. Block tile 128x128, BK=16, 256 thr (8 warps).
// Warp tile 64x32: warp rows wr=warpId&1 (2x64), cols wc=warpId>>1 (4x32).
// mma.m16n8k8: 4 m-tiles x 4 n-tiles per warp per k8.
template <bool RELU, bool RES>
__global__ __launch_bounds__(256, 2) void gemm_tf32_kernel(
    const float* __restrict__ A, const float* __restrict__ B,
    const float* __restrict__ bias, const float* __restrict__ res,
    float* __restrict__ C, int M, int N, int K)
{
    __shared__ float As[2][128][20];   // [buf][row][k]  pad 16->20 (conflict-free frag loads)
    __shared__ float Bs[2][16][132];   // [buf][k][col]  pad 128->132

    const int tid = threadIdx.x;
    const int warpId = tid >> 5, lane = tid & 31;
    const int g = lane >> 2, t = lane & 3;
    const int wr = warpId & 1;         // 0..1 (64-row groups)
    const int wc = warpId >> 1;        // 0..3 (32-col groups)
    const int rowStart = blockIdx.y * 128;
    const int colStart = blockIdx.x * 128;

    // global-load mapping (each thread: 2 float4 for A, 2 float4 for B)
    const int aRow = tid >> 2;                 // 0..63 (and +64)
    const int aC4  = (tid & 3) * 4;            // k offset 0/4/8/12
    const int bK   = tid >> 5;                 // 0..7 (and +8)
    const int bC4  = (tid & 31) * 4;           // col offset

    const float* Ap0 = A + (size_t)(rowStart + aRow)      * K + aC4;
    const float* Ap1 = A + (size_t)(rowStart + aRow + 64) * K + aC4;
    const float* Bp0 = B + (size_t)bK       * N + colStart + bC4;
    const float* Bp1 = B + (size_t)(bK + 8) * N + colStart + bC4;

    float acc[4][4][4];
#pragma unroll
    for (int mt = 0; mt < 4; mt++)
#pragma unroll
        for (int nt = 0; nt < 4; nt++)
#pragma unroll
            for (int r = 0; r < 4; r++) acc[mt][nt][r] = 0.f;

    // prologue: stage 0 -> buf 0 (convert to tf32 at smem store)
    {
        float4 a0 = *reinterpret_cast<const float4*>(Ap0);
        float4 a1 = *reinterpret_cast<const float4*>(Ap1);
        float4 b0 = *reinterpret_cast<const float4*>(Bp0);
        float4 b1 = *reinterpret_cast<const float4*>(Bp1);
        *reinterpret_cast<float4*>(&As[0][aRow][aC4]) =
            make_float4(tf32r(a0.x), tf32r(a0.y), tf32r(a0.z), tf32r(a0.w));
        *reinterpret_cast<float4*>(&As[0][aRow + 64][aC4]) =
            make_float4(tf32r(a1.x), tf32r(a1.y), tf32r(a1.z), tf32r(a1.w));
        *reinterpret_cast<float4*>(&Bs[0][bK][bC4]) =
            make_float4(tf32r(b0.x), tf32r(b0.y), tf32r(b0.z), tf32r(b0.w));
        *reinterpret_cast<float4*>(&Bs[0][bK + 8][bC4]) =
            make_float4(tf32r(b1.x), tf32r(b1.y), tf32r(b1.z), tf32r(b1.w));
    }
    __syncthreads();

    int buf = 0;
    for (int k0 = 16; k0 <= K; k0 += 16) {
        // prefetch next stage into registers
        float4 pa0, pa1, pb0, pb1;
        const bool more = (k0 < K);
        if (more) {
            pa0 = *reinterpret_cast<const float4*>(Ap0 + k0);
            pa1 = *reinterpret_cast<const float4*>(Ap1 + k0);
            pb0 = *reinterpret_cast<const float4*>(Bp0 + (size_t)k0 * N);
            pb1 = *reinterpret_cast<const float4*>(Bp1 + (size_t)k0 * N);
        }

        // compute: two k8 steps on current buffer
#pragma unroll
        for (int k8 = 0; k8 < 16; k8 += 8) {
            uint32_t af[4][4];
#pragma unroll
            for (int mt = 0; mt < 4; mt++) {
                const int r = wr * 64 + mt * 16 + g;
                af[mt][0] = __float_as_uint(As[buf][r    ][k8 + t]);
                af[mt][1] = __float_as_uint(As[buf][r + 8][k8 + t]);
                af[mt][2] = __float_as_uint(As[buf][r    ][k8 + t + 4]);
                af[mt][3] = __float_as_uint(As[buf][r + 8][k8 + t + 4]);
            }
            uint32_t bf[4][2];
#pragma unroll
            for (int nt = 0; nt < 4; nt++) {
                const int c = wc * 32 + nt * 8 + g;
                bf[nt][0] = __float_as_uint(Bs[buf][k8 + t    ][c]);
                bf[nt][1] = __float_as_uint(Bs[buf][k8 + t + 4][c]);
            }
#pragma unroll
            for (int mt = 0; mt < 4; mt++)
#pragma unroll
                for (int nt = 0; nt < 4; nt++)
                    mma_tf32(acc[mt][nt],
                             af[mt][0], af[mt][1], af[mt][2], af[mt][3],
                             bf[nt][0], bf[nt][1]);
        }

        if (more) {
            const int nb = buf ^ 1;
            __syncthreads();   // everyone done reading buf^1 from 2 stages ago
            *reinterpret_cast<float4*>(&As[nb][aRow][aC4]) =
                make_float4(tf32r(pa0.x), tf32r(pa0.y), tf32r(pa0.z), tf32r(pa0.w));
            *reinterpret_cast<float4*>(&As[nb][aRow + 64][aC4]) =
                make_float4(tf32r(pa1.x), tf32r(pa1.y), tf32r(pa1.z), tf32r(pa1.w));
            *reinterpret_cast<float4*>(&Bs[nb][bK][bC4]) =
                make_float4(tf32r(pb0.x), tf32r(pb0.y), tf32r(pb0.z), tf32r(pb0.w));
            *reinterpret_cast<float4*>(&Bs[nb][bK + 8][bC4]) =
                make_float4(tf32r(pb1.x), tf32r(pb1.y), tf32r(pb1.z), tf32r(pb1.w));
            __syncthreads();
            buf = nb;
        }
    }

    // epilogue: c0,c1 = (g, 2t),(g, 2t+1); c2,c3 = (g+8, 2t),(g+8, 2t+1)
#pragma unroll
    for (int mt = 0; mt < 4; mt++) {
        const int r0 = rowStart + wr * 64 + mt * 16 + g;
#pragma unroll
        for (int nt = 0; nt < 4; nt++) {
            const int c0 = colStart + wc * 32 + nt * 8 + t * 2;
            float bx = bias[c0], by = bias[c0 + 1];
            float v0 = acc[mt][nt][0] + bx;
            float v1 = acc[mt][nt][1] + by;
            float v2 = acc[mt][nt][2] + bx;
            float v3 = acc[mt][nt][3] + by;
            const size_t off0 = (size_t)r0 * N + c0;
            const size_t off1 = (size_t)(r0 + 8) * N + c0;
            if (RES) {
                float2 q0 = *reinterpret_cast<const float2*>(&res[off0]);
                float2 q1 = *reinterpret_cast<const float2*>(&res[off1]);
                v0 += q0.x; v1 += q0.y; v2 += q1.x; v3 += q1.y;
            }
            if (RELU) {
                v0 = fmaxf(v0, 0.f); v1 = fmaxf(v1, 0.f);
                v2 = fmaxf(v2, 0.f); v3 = fmaxf(v3, 0.f);
            }
            *reinterpret_cast<float2*>(&C[off0]) = make_float2(v0, v1);
            *reinterpret_cast<float2*>(&C[off1]) = make_float2(v2, v3);
        }
    }
}

// ---------------- flash attention (fp32, register-tiled) -------------------
// q,k,v,out: [NB, SEQ, EMB], head h at cols h*64..h*64+63.
// grid: (SEQ/64, NH, NB); 256 threads. 64x64 Q-tile x 64 K-tile.
__global__ __launch_bounds__(256) void attn_kernel(
    const float* __restrict__ q, const float* __restrict__ k,
    const float* __restrict__ v, float* __restrict__ out)
{
    __shared__ float Qs[64][64];
    __shared__ float KV[64][64];
    __shared__ float Ps[64][64];

    const int qt = blockIdx.x, h = blockIdx.y, n = blockIdx.z;
    const int tid = threadIdx.x;
    const int ty = tid >> 4, tx = tid & 15;
    const int r0 = ty * 4, c0 = tx * 4;
    const size_t base = ((size_t)n * SEQ) * EMB + h * HD;

    {
        int u = tid;
#pragma unroll
        for (int it = 0; it < 4; it++, u += 256) {
            const int rr = u >> 4, d4 = u & 15;
            float4 t = *reinterpret_cast<const float4*>(
                &q[base + (size_t)(qt * 64 + rr) * EMB + d4 * 4]);
            t.x *= 0.125f; t.y *= 0.125f; t.z *= 0.125f; t.w *= 0.125f;
            *reinterpret_cast<float4*>(&Qs[rr][d4 * 4]) = t;
        }
    }

    float m[4], l[4], o[4][4];
#pragma unroll
    for (int i = 0; i < 4; i++) {
        m[i] = -INFINITY; l[i] = 0.f;
#pragma unroll
        for (int j = 0; j < 4; j++) o[i][j] = 0.f;
    }

    for (int kt = 0; kt < SEQ / 64; kt++) {
        __syncthreads();
        {
            int u = tid;
#pragma unroll
            for (int it = 0; it < 4; it++, u += 256) {
                const int cc = u >> 4, d4 = u & 15;
                float4 t = *reinterpret_cast<const float4*>(
                    &k[base + (size_t)(kt * 64 + cc) * EMB + d4 * 4]);
                *reinterpret_cast<float4*>(&KV[cc][(d4 ^ (cc >> 2)) * 4]) = t;
            }
        }
        __syncthreads();

        float s[4][4];
#pragma unroll
        for (int i = 0; i < 4; i++)
#pragma unroll
            for (int j = 0; j < 4; j++) s[i][j] = 0.f;

#pragma unroll
        for (int d4 = 0; d4 < 16; d4++) {
            float4 kf[4];
#pragma unroll
            for (int j = 0; j < 4; j++) {
                const int cc = c0 + j;
                kf[j] = *reinterpret_cast<const float4*>(
                    &KV[cc][(d4 ^ (cc >> 2)) * 4]);
            }
#pragma unroll
            for (int i = 0; i < 4; i++) {
                float4 qf = *reinterpret_cast<const float4*>(&Qs[r0 + i][d4 * 4]);
#pragma unroll
                for (int j = 0; j < 4; j++) {
                    s[i][j] = fmaf(qf.x, kf[j].x, s[i][j]);
                    s[i][j] = fmaf(qf.y, kf[j].y, s[i][j]);
                    s[i][j] = fmaf(qf.z, kf[j].z, s[i][j]);
                    s[i][j] = fmaf(qf.w, kf[j].w, s[i][j]);
                }
            }
        }

#pragma unroll
        for (int i = 0; i < 4; i++) {
            float mt = fmaxf(fmaxf(s[i][0], s[i][1]), fmaxf(s[i][2], s[i][3]));
            mt = fmaxf(mt, __shfl_xor_sync(0xffffffffu, mt, 1));
            mt = fmaxf(mt, __shfl_xor_sync(0xffffffffu, mt, 2));
            mt = fmaxf(mt, __shfl_xor_sync(0xffffffffu, mt, 4));
            mt = fmaxf(mt, __shfl_xor_sync(0xffffffffu, mt, 8));
            const float mn = fmaxf(m[i], mt);
            const float corr = __expf(m[i] - mn);
            float ls = 0.f;
#pragma unroll
            for (int j = 0; j < 4; j++) {
                const float p = __expf(s[i][j] - mn);
                s[i][j] = p; ls += p;
            }
            ls += __shfl_xor_sync(0xffffffffu, ls, 1);
            ls += __shfl_xor_sync(0xffffffffu, ls, 2);
            ls += __shfl_xor_sync(0xffffffffu, ls, 4);
            ls += __shfl_xor_sync(0xffffffffu, ls, 8);
            l[i] = l[i] * corr + ls;
            m[i] = mn;
#pragma unroll
            for (int j = 0; j < 4; j++) o[i][j] *= corr;
            *reinterpret_cast<float4*>(&Ps[r0 + i][c0]) =
                make_float4(s[i][0], s[i][1], s[i][2], s[i][3]);
        }
        __syncthreads();

        {
            int u = tid;
#pragma unroll
            for (int it = 0; it < 4; it++, u += 256) {
                const int cc = u >> 4, d4 = u & 15;
                float4 t = *reinterpret_cast<const float4*>(
                    &v[base + (size_t)(kt * 64 + cc) * EMB + d4 * 4]);
                *reinterpret_cast<float4*>(&KV[cc][(d4 ^ (cc >> 2)) * 4]) = t;
            }
        }
        __syncthreads();

#pragma unroll
        for (int j4 = 0; j4 < 16; j4++) {
            float4 vf[4];
#pragma unroll
            for (int tt = 0; tt < 4; tt++) {
                const int cc = j4 * 4 + tt;
                vf[tt] = *reinterpret_cast<const float4*>(
                    &KV[cc][(tx ^ (cc >> 2)) * 4]);
            }
#pragma unroll
            for (int i = 0; i < 4; i++) {
                float4 pf = *reinterpret_cast<const float4*>(&Ps[r0 + i][j4 * 4]);
                o[i][0] = fmaf(pf.x, vf[0].x, o[i][0]);
                o[i][1] = fmaf(pf.x, vf[0].y, o[i][1]);
                o[i][2] = fmaf(pf.x, vf[0].z, o[i][2]);
                o[i][3] = fmaf(pf.x, vf[0].w, o[i][3]);
                o[i][0] = fmaf(pf.y, vf[1].x, o[i][0]);
                o[i][1] = fmaf(pf.y, vf[1].y, o[i][1]);
                o[i][2] = fmaf(pf.y, vf[1].z, o[i][2]);
                o[i][3] = fmaf(pf.y, vf[1].w, o[i][3]);
                o[i][0] = fmaf(pf.z, vf[2].x, o[i][0]);
                o[i][1] = fmaf(pf.z, vf[2].y, o[i][1]);
                o[i][2] = fmaf(pf.z, vf[2].z, o[i][2]);
                o[i][3] = fmaf(pf.z, vf[2].w, o[i][3]);
                o[i][0] = fmaf(pf.w, vf[3].x, o[i][0]);
                o[i][1] = fmaf(pf.w, vf[3].y, o[i][1]);
                o[i][2] = fmaf(pf.w, vf[3].z, o[i][2]);
                o[i][3] = fmaf(pf.w, vf[3].w, o[i][3]);
            }
        }
    }

#pragma unroll
    for (int i = 0; i < 4; i++) {
        const float inv = 1.f / l[i];
        float4 t = make_float4(o[i][0] * inv, o[i][1] * inv,
                               o[i][2] * inv, o[i][3] * inv);
        *reinterpret_cast<float4*>(
            &out[base + (size_t)(qt * 64 + r0 + i) * EMB + c0]) = t;
    }
}

// ---------------- logits + GAN loss -----------------------------------------
__global__ void loss_kernel(const float* __restrict__ xfin,
                            const float* __restrict__ wlr,
                            const float* __restrict__ blr,
                            float* __restrict__ out)
{
    __shared__ float slog[4];
    const int warp = threadIdx.x >> 5, lane = threadIdx.x & 31;
    if (warp < 4) {
        const float* xr = xfin + (size_t)warp * SEQ * EMB;  // token 0
        float s = 0.f;
        for (int i = lane; i < EMB; i += 32) s = fmaf(xr[i], wlr[i], s);
#pragma unroll
        for (int off = 16; off; off >>= 1)
            s += __shfl_xor_sync(0xffffffffu, s, off);
        if (lane == 0) slog[warp] = s + blr[0];
    }
    __syncthreads();
    if (threadIdx.x == 0) {
        auto sp = [](float t) {
            return fmaxf(t, 0.f) + log1pf(expf(-fabsf(t)));
        };
        float loss_real = 0.5f * (sp(-slog[0]) + sp(-slog[1]));
        float loss_fake = 0.5f * (sp( slog[2]) + sp( slog[3]));
        out[0] = 0.5f * (loss_fake + loss_real);
        out[1] = loss_fake;
    }
}

// ---------------- launch ----------------------------------------------------
extern "C" void kernel_launch(void* const* d_in, const int* in_sizes, int n_in,
                              void* d_out, int out_size)
{
    const float* x     = (const float*)d_in[0];
    const float* wq    = (const float*)d_in[1];
    const float* bq    = (const float*)d_in[2];
    const float* wk    = (const float*)d_in[3];
    const float* bk    = (const float*)d_in[4];
    const float* wv    = (const float*)d_in[5];
    const float* bv    = (const float*)d_in[6];
    const float* wo    = (const float*)d_in[7];
    const float* bo    = (const float*)d_in[8];
    const float* ln1_g = (const float*)d_in[9];
    const float* ln1_b = (const float*)d_in[10];
    const float* ln2_g = (const float*)d_in[11];
    const float* ln2_b = (const float*)d_in[12];
    const float* w1    = (const float*)d_in[13];
    const float* b1    = (const float*)d_in[14];
    const float* w2    = (const float*)d_in[15];
    const float* b2    = (const float*)d_in[16];
    const float* wlr   = (const float*)d_in[17];
    const float* blr   = (const float*)d_in[18];
    float* out = (float*)d_out;

    float *xn, *q, *k, *v, *att, *x1, *xn2, *ffn;
    cudaGetSymbolAddress((void**)&xn,  g_xn);
    cudaGetSymbolAddress((void**)&q,   g_q);
    cudaGetSymbolAddress((void**)&k,   g_k);
    cudaGetSymbolAddress((void**)&v,   g_v);
    cudaGetSymbolAddress((void**)&att, g_att);
    cudaGetSymbolAddress((void**)&x1,  g_x1);
    cudaGetSymbolAddress((void**)&xn2, g_xn2);
    cudaGetSymbolAddress((void**)&ffn, g_ffn);

    // 1) LN1
    ln_kernel<<<MROWS, 256>>>(x, ln1_g, ln1_b, xn);

    // 2) Q,K,V projections (tf32 tensor cores)
    dim3 gProj(EMB / 128, MROWS / 128);
    gemm_tf32_kernel<false, false><<<gProj, 256>>>(xn, wq, bq, nullptr, q, MROWS, EMB, EMB);
    gemm_tf32_kernel<false, false><<<gProj, 256>>>(xn, wk, bk, nullptr, k, MROWS, EMB, EMB);
    gemm_tf32_kernel<false, false><<<gProj, 256>>>(xn, wv, bv, nullptr, v, MROWS, EMB, EMB);

    // 3) attention
    dim3 gAttn(SEQ / 64, NH, NB);
    attn_kernel<<<gAttn, 256>>>(q, k, v, att);

    // 4) out-proj + residual -> x1
    gemm_tf32_kernel<false, true><<<gProj, 256>>>(att, wo, bo, x, x1, MROWS, EMB, EMB);

    // 5) LN2
    ln_kernel<<<MROWS, 256>>>(x1, ln2_g, ln2_b, xn2);

    // 6) FFN1 with ReLU
    dim3 gFF1(FF / 128, MROWS / 128);
    gemm_tf32_kernel<true, false><<<gFF1, 256>>>(xn2, w1, b1, nullptr, ffn, MROWS, FF, EMB);

    // 7) FFN2 + residual -> final x (directly into d_out)
    gemm_tf32_kernel<false, true><<<gProj, 256>>>(ffn, w2, b2, x1, out, MROWS, EMB, FF);

    // 8) logits + losses
    loss_kernel<<<1, 128>>>(out, wlr, blr, out + X_SIZE);
}

// round 5
// speedup vs baseline: 4.6374x; 1.4940x over previous
#include <cuda_runtime.h>
#include <cuda_bf16.h>
#include <math.h>
#include <stdint.h>

// Problem dims (fixed by reference)
#define NB 4
#define SEQ 2048
#define EMB 1024
#define NH 16
#define HD 64
#define FF 4096
#define MROWS (NB * SEQ)          // 8192
#define X_SIZE (NB * SEQ * EMB)   // 8388608

// ---------------- scratch (device globals; no allocation allowed) ----------
__device__ float g_xn [MROWS * EMB];
__device__ float g_q  [MROWS * EMB];
__device__ float g_k  [MROWS * EMB];
__device__ float g_v  [MROWS * EMB];
__device__ float g_att[MROWS * EMB];
__device__ float g_x1 [MROWS * EMB];
__device__ float g_xn2[MROWS * EMB];
__device__ float g_ffn[MROWS * FF];

// ---------------- helpers ---------------------------------------------------
__device__ __forceinline__ float tf32r(float x) {
    uint32_t u;
    asm("cvt.rna.tf32.f32 %0, %1;" : "=r"(u) : "f"(x));
    return __uint_as_float(u);
}

__device__ __forceinline__ void mma_tf32(float d[4],
                                         uint32_t a0, uint32_t a1,
                                         uint32_t a2, uint32_t a3,
                                         uint32_t b0, uint32_t b1) {
    asm volatile(
        "mma.sync.aligned.m16n8k8.row.col.f32.tf32.tf32.f32 "
        "{%0,%1,%2,%3}, {%4,%5,%6,%7}, {%8,%9}, {%0,%1,%2,%3};"
        : "+f"(d[0]), "+f"(d[1]), "+f"(d[2]), "+f"(d[3])
        : "r"(a0), "r"(a1), "r"(a2), "r"(a3), "r"(b0), "r"(b1));
}

// ---------------- layernorm: one block per row of 1024 ---------------------
__global__ __launch_bounds__(256) void ln_kernel(
    const float* __restrict__ in, const float* __restrict__ g,
    const float* __restrict__ b, float* __restrict__ out)
{
    const int row = blockIdx.x;
    const float* xr = in + (size_t)row * EMB;
    float* orow = out + (size_t)row * EMB;
    const int tid = threadIdx.x;

    float vals[4];
    float s = 0.f, sq = 0.f;
#pragma unroll
    for (int i = 0; i < 4; i++) {
        float v = xr[i * 256 + tid];
        vals[i] = v; s += v; sq += v * v;
    }
    __shared__ float red[16];
#pragma unroll
    for (int off = 16; off; off >>= 1) {
        s  += __shfl_xor_sync(0xffffffffu, s,  off);
        sq += __shfl_xor_sync(0xffffffffu, sq, off);
    }
    const int warp = tid >> 5, lane = tid & 31;
    if (lane == 0) { red[warp] = s; red[warp + 8] = sq; }
    __syncthreads();
    if (warp == 0) {
        float ss = (lane < 8) ? red[lane] : 0.f;
        float qq = (lane < 8) ? red[lane + 8] : 0.f;
#pragma unroll
        for (int off = 4; off; off >>= 1) {
            ss += __shfl_xor_sync(0xffffffffu, ss, off);
            qq += __shfl_xor_sync(0xffffffffu, qq, off);
        }
        if (lane == 0) { red[0] = ss; red[1] = qq; }
    }
    __syncthreads();
    const float mean = red[0] * (1.0f / EMB);
    const float var  = red[1] * (1.0f / EMB) - mean * mean;
    const float inv  = rsqrtf(var + 1e-5f);
#pragma unroll
    for (int i = 0; i < 4; i++) {
        int idx = i * 256 + tid;
        orow[idx] = (vals[i] - mean) * inv * g[idx] + b[idx];
    }
}

// ---------------- tf32 tensor-core GEMM body --------------------------------
// A [M,K] rm, B [K,N] rm. Block tile 128x128, BK=16, 256 thr (8 warps).
// Warp tile 64x32. Single __syncthreads per main-loop iteration.
template <bool RELU, bool RES>
__device__ __forceinline__ void gemm_body(
    const float* __restrict__ A, const float* __restrict__ B,
    const float* __restrict__ bias, const float* __restrict__ res,
    float* __restrict__ C, int M, int N, int K, int bx, int by)
{
    __shared__ float As[2][128][20];   // [buf][row][k]
    __shared__ float Bs[2][16][132];   // [buf][k][col]

    const int tid = threadIdx.x;
    const int warpId = tid >> 5, lane = tid & 31;
    const int g = lane >> 2, t = lane & 3;
    const int wr = warpId & 1;
    const int wc = warpId >> 1;
    const int rowStart = by * 128;
    const int colStart = bx * 128;

    const int aRow = tid >> 2;
    const int aC4  = (tid & 3) * 4;
    const int bK   = tid >> 5;
    const int bC4  = (tid & 31) * 4;

    const float* Ap0 = A + (size_t)(rowStart + aRow)      * K + aC4;
    const float* Ap1 = A + (size_t)(rowStart + aRow + 64) * K + aC4;
    const float* Bp0 = B + (size_t)bK       * N + colStart + bC4;
    const float* Bp1 = B + (size_t)(bK + 8) * N + colStart + bC4;

    float acc[4][4][4];
#pragma unroll
    for (int mt = 0; mt < 4; mt++)
#pragma unroll
        for (int nt = 0; nt < 4; nt++)
#pragma unroll
            for (int r = 0; r < 4; r++) acc[mt][nt][r] = 0.f;

    // prologue: stage 0 -> buf 0
    {
        float4 a0 = *reinterpret_cast<const float4*>(Ap0);
        float4 a1 = *reinterpret_cast<const float4*>(Ap1);
        float4 b0 = *reinterpret_cast<const float4*>(Bp0);
        float4 b1 = *reinterpret_cast<const float4*>(Bp1);
        *reinterpret_cast<float4*>(&As[0][aRow][aC4]) =
            make_float4(tf32r(a0.x), tf32r(a0.y), tf32r(a0.z), tf32r(a0.w));
        *reinterpret_cast<float4*>(&As[0][aRow + 64][aC4]) =
            make_float4(tf32r(a1.x), tf32r(a1.y), tf32r(a1.z), tf32r(a1.w));
        *reinterpret_cast<float4*>(&Bs[0][bK][bC4]) =
            make_float4(tf32r(b0.x), tf32r(b0.y), tf32r(b0.z), tf32r(b0.w));
        *reinterpret_cast<float4*>(&Bs[0][bK + 8][bC4]) =
            make_float4(tf32r(b1.x), tf32r(b1.y), tf32r(b1.z), tf32r(b1.w));
    }
    __syncthreads();

    int buf = 0;
    for (int k0 = 16; k0 <= K; k0 += 16) {
        float4 pa0, pa1, pb0, pb1;
        const bool more = (k0 < K);
        if (more) {
            pa0 = *reinterpret_cast<const float4*>(Ap0 + k0);
            pa1 = *reinterpret_cast<const float4*>(Ap1 + k0);
            pb0 = *reinterpret_cast<const float4*>(Bp0 + (size_t)k0 * N);
            pb1 = *reinterpret_cast<const float4*>(Bp1 + (size_t)k0 * N);
        }

#pragma unroll
        for (int k8 = 0; k8 < 16; k8 += 8) {
            uint32_t af[4][4];
#pragma unroll
            for (int mt = 0; mt < 4; mt++) {
                const int r = wr * 64 + mt * 16 + g;
                af[mt][0] = __float_as_uint(As[buf][r    ][k8 + t]);
                af[mt][1] = __float_as_uint(As[buf][r + 8][k8 + t]);
                af[mt][2] = __float_as_uint(As[buf][r    ][k8 + t + 4]);
                af[mt][3] = __float_as_uint(As[buf][r + 8][k8 + t + 4]);
            }
            uint32_t bf[4][2];
#pragma unroll
            for (int nt = 0; nt < 4; nt++) {
                const int c = wc * 32 + nt * 8 + g;
                bf[nt][0] = __float_as_uint(Bs[buf][k8 + t    ][c]);
                bf[nt][1] = __float_as_uint(Bs[buf][k8 + t + 4][c]);
            }
#pragma unroll
            for (int mt = 0; mt < 4; mt++)
#pragma unroll
                for (int nt = 0; nt < 4; nt++)
                    mma_tf32(acc[mt][nt],
                             af[mt][0], af[mt][1], af[mt][2], af[mt][3],
                             bf[nt][0], bf[nt][1]);
        }

        if (more) {
            const int nb = buf ^ 1;
            // write next stage while others may still read current buf — safe
            *reinterpret_cast<float4*>(&As[nb][aRow][aC4]) =
                make_float4(tf32r(pa0.x), tf32r(pa0.y), tf32r(pa0.z), tf32r(pa0.w));
            *reinterpret_cast<float4*>(&As[nb][aRow + 64][aC4]) =
                make_float4(tf32r(pa1.x), tf32r(pa1.y), tf32r(pa1.z), tf32r(pa1.w));
            *reinterpret_cast<float4*>(&Bs[nb][bK][bC4]) =
                make_float4(tf32r(pb0.x), tf32r(pb0.y), tf32r(pb0.z), tf32r(pb0.w));
            *reinterpret_cast<float4*>(&Bs[nb][bK + 8][bC4]) =
                make_float4(tf32r(pb1.x), tf32r(pb1.y), tf32r(pb1.z), tf32r(pb1.w));
            __syncthreads();
            buf = nb;
        }
    }

#pragma unroll
    for (int mt = 0; mt < 4; mt++) {
        const int r0 = rowStart + wr * 64 + mt * 16 + g;
#pragma unroll
        for (int nt = 0; nt < 4; nt++) {
            const int c0 = colStart + wc * 32 + nt * 8 + t * 2;
            float bx0 = bias[c0], by0 = bias[c0 + 1];
            float v0 = acc[mt][nt][0] + bx0;
            float v1 = acc[mt][nt][1] + by0;
            float v2 = acc[mt][nt][2] + bx0;
            float v3 = acc[mt][nt][3] + by0;
            const size_t off0 = (size_t)r0 * N + c0;
            const size_t off1 = (size_t)(r0 + 8) * N + c0;
            if (RES) {
                float2 q0 = *reinterpret_cast<const float2*>(&res[off0]);
                float2 q1 = *reinterpret_cast<const float2*>(&res[off1]);
                v0 += q0.x; v1 += q0.y; v2 += q1.x; v3 += q1.y;
            }
            if (RELU) {
                v0 = fmaxf(v0, 0.f); v1 = fmaxf(v1, 0.f);
                v2 = fmaxf(v2, 0.f); v3 = fmaxf(v3, 0.f);
            }
            *reinterpret_cast<float2*>(&C[off0]) = make_float2(v0, v1);
            *reinterpret_cast<float2*>(&C[off1]) = make_float2(v2, v3);
        }
    }
}

template <bool RELU, bool RES>
__global__ __launch_bounds__(256, 2) void gemm_tf32_kernel(
    const float* __restrict__ A, const float* __restrict__ B,
    const float* __restrict__ bias, const float* __restrict__ res,
    float* __restrict__ C, int M, int N, int K)
{
    gemm_body<RELU, RES>(A, B, bias, res, C, M, N, K, blockIdx.x, blockIdx.y);
}

// Fused QKV: grid.z selects weight/bias/output.
__global__ __launch_bounds__(256, 2) void gemm_qkv_kernel(
    const float* __restrict__ A,
    const float* __restrict__ w0, const float* __restrict__ w1, const float* __restrict__ w2,
    const float* __restrict__ b0, const float* __restrict__ b1, const float* __restrict__ b2,
    float* __restrict__ c0, float* __restrict__ c1, float* __restrict__ c2)
{
    const int z = blockIdx.z;
    const float* B = (z == 0) ? w0 : (z == 1) ? w1 : w2;
    const float* bias = (z == 0) ? b0 : (z == 1) ? b1 : b2;
    float* C = (z == 0) ? c0 : (z == 1) ? c1 : c2;
    gemm_body<false, false>(A, B, bias, nullptr, C, MROWS, EMB, EMB,
                            blockIdx.x, blockIdx.y);
}

// ---------------- flash attention (tf32 tensor cores) ----------------------
// q,k,v,out: [NB, SEQ, EMB], head h at cols h*64..h*64+63.
// grid: (SEQ/64, NH, NB); 128 threads (4 warps), each warp = 16 query rows.
// Q fragments live in registers for the whole K loop. K and V share one
// smem buffer; P round-trips through smem to become the A operand of PV.
__global__ __launch_bounds__(128, 3) void attn_mma_kernel(
    const float* __restrict__ q, const float* __restrict__ k,
    const float* __restrict__ v, float* __restrict__ out)
{
    __shared__ float KV[64][68];
    __shared__ float Ps[64][68];

    const int qt = blockIdx.x, h = blockIdx.y, n = blockIdx.z;
    const int tid = threadIdx.x;
    const int warp = tid >> 5, lane = tid & 31;
    const int g = lane >> 2, t = lane & 3;
    const int w16 = warp * 16;
    const size_t base = ((size_t)n * SEQ) * EMB + h * HD;

    // stage Q (scaled, tf32) into KV, then build register fragments
#pragma unroll
    for (int it = 0; it < 8; it++) {
        const int u = tid + it * 128;
        const int rr = u >> 4, d4 = (u & 15) * 4;
        float4 tq = *reinterpret_cast<const float4*>(
            &q[base + (size_t)(qt * 64 + rr) * EMB + d4]);
        *reinterpret_cast<float4*>(&KV[rr][d4]) =
            make_float4(tf32r(tq.x * 0.125f), tf32r(tq.y * 0.125f),
                        tf32r(tq.z * 0.125f), tf32r(tq.w * 0.125f));
    }
    __syncthreads();

    uint32_t qf[8][4];
#pragma unroll
    for (int k8 = 0; k8 < 8; k8++) {
        qf[k8][0] = __float_as_uint(KV[w16 + g    ][k8 * 8 + t    ]);
        qf[k8][1] = __float_as_uint(KV[w16 + g + 8][k8 * 8 + t    ]);
        qf[k8][2] = __float_as_uint(KV[w16 + g    ][k8 * 8 + t + 4]);
        qf[k8][3] = __float_as_uint(KV[w16 + g + 8][k8 * 8 + t + 4]);
    }

    float m0 = -INFINITY, m1 = -INFINITY, l0 = 0.f, l1 = 0.f;
    float o[8][4];
#pragma unroll
    for (int nt = 0; nt < 8; nt++)
#pragma unroll
        for (int r = 0; r < 4; r++) o[nt][r] = 0.f;

    for (int kt = 0; kt < SEQ / 64; kt++) {
        __syncthreads();   // qf built (iter 0) / prev PV done with KV & Ps
        // ---- load K tile (tf32) ----
#pragma unroll
        for (int it = 0; it < 8; it++) {
            const int u = tid + it * 128;
            const int cc = u >> 4, d4 = (u & 15) * 4;
            float4 tk = *reinterpret_cast<const float4*>(
                &k[base + (size_t)(kt * 64 + cc) * EMB + d4]);
            *reinterpret_cast<float4*>(&KV[cc][d4]) =
                make_float4(tf32r(tk.x), tf32r(tk.y), tf32r(tk.z), tf32r(tk.w));
        }
        __syncthreads();

        // ---- S = Q K^T ----
        float s[8][4];
#pragma unroll
        for (int nt = 0; nt < 8; nt++)
#pragma unroll
            for (int r = 0; r < 4; r++) s[nt][r] = 0.f;

#pragma unroll
        for (int k8 = 0; k8 < 8; k8++) {
#pragma unroll
            for (int nt = 0; nt < 8; nt++) {
                const int c = nt * 8 + g;
                uint32_t b0 = __float_as_uint(KV[c][k8 * 8 + t    ]);
                uint32_t b1 = __float_as_uint(KV[c][k8 * 8 + t + 4]);
                mma_tf32(s[nt], qf[k8][0], qf[k8][1], qf[k8][2], qf[k8][3],
                         b0, b1);
            }
        }

        // ---- online softmax (rows g and g+8 of this warp's 16) ----
        float mt0 = -INFINITY, mt1 = -INFINITY;
#pragma unroll
        for (int nt = 0; nt < 8; nt++) {
            mt0 = fmaxf(mt0, fmaxf(s[nt][0], s[nt][1]));
            mt1 = fmaxf(mt1, fmaxf(s[nt][2], s[nt][3]));
        }
        mt0 = fmaxf(mt0, __shfl_xor_sync(0xffffffffu, mt0, 1));
        mt0 = fmaxf(mt0, __shfl_xor_sync(0xffffffffu, mt0, 2));
        mt1 = fmaxf(mt1, __shfl_xor_sync(0xffffffffu, mt1, 1));
        mt1 = fmaxf(mt1, __shfl_xor_sync(0xffffffffu, mt1, 2));

        const float mn0 = fmaxf(m0, mt0), mn1 = fmaxf(m1, mt1);
        const float c0 = __expf(m0 - mn0), c1 = __expf(m1 - mn1);
        float ls0 = 0.f, ls1 = 0.f;
#pragma unroll
        for (int nt = 0; nt < 8; nt++) {
            const float p0 = __expf(s[nt][0] - mn0);
            const float p1 = __expf(s[nt][1] - mn0);
            const float p2 = __expf(s[nt][2] - mn1);
            const float p3 = __expf(s[nt][3] - mn1);
            ls0 += p0 + p1; ls1 += p2 + p3;
            *reinterpret_cast<float2*>(&Ps[w16 + g    ][nt * 8 + t * 2]) =
                make_float2(tf32r(p0), tf32r(p1));
            *reinterpret_cast<float2*>(&Ps[w16 + g + 8][nt * 8 + t * 2]) =
                make_float2(tf32r(p2), tf32r(p3));
        }
        ls0 += __shfl_xor_sync(0xffffffffu, ls0, 1);
        ls0 += __shfl_xor_sync(0xffffffffu, ls0, 2);
        ls1 += __shfl_xor_sync(0xffffffffu, ls1, 1);
        ls1 += __shfl_xor_sync(0xffffffffu, ls1, 2);
        l0 = l0 * c0 + ls0; l1 = l1 * c1 + ls1;
        m0 = mn0; m1 = mn1;
#pragma unroll
        for (int nt = 0; nt < 8; nt++) {
            o[nt][0] *= c0; o[nt][1] *= c0;
            o[nt][2] *= c1; o[nt][3] *= c1;
        }
        __syncthreads();   // Ps complete; S-mma done reading KV

        // ---- load V tile into KV (tf32) ----
#pragma unroll
        for (int it = 0; it < 8; it++) {
            const int u = tid + it * 128;
            const int cc = u >> 4, d4 = (u & 15) * 4;
            float4 tv = *reinterpret_cast<const float4*>(
                &v[base + (size_t)(kt * 64 + cc) * EMB + d4]);
            *reinterpret_cast<float4*>(&KV[cc][d4]) =
                make_float4(tf32r(tv.x), tf32r(tv.y), tf32r(tv.z), tf32r(tv.w));
        }
        __syncthreads();

        // ---- O += P V ----
#pragma unroll
        for (int k8 = 0; k8 < 8; k8++) {
            uint32_t a0 = __float_as_uint(Ps[w16 + g    ][k8 * 8 + t    ]);
            uint32_t a1 = __float_as_uint(Ps[w16 + g + 8][k8 * 8 + t    ]);
            uint32_t a2 = __float_as_uint(Ps[w16 + g    ][k8 * 8 + t + 4]);
            uint32_t a3 = __float_as_uint(Ps[w16 + g + 8][k8 * 8 + t + 4]);
#pragma unroll
            for (int nt = 0; nt < 8; nt++) {
                uint32_t b0 = __float_as_uint(KV[k8 * 8 + t    ][nt * 8 + g]);
                uint32_t b1 = __float_as_uint(KV[k8 * 8 + t + 4][nt * 8 + g]);
                mma_tf32(o[nt], a0, a1, a2, a3, b0, b1);
            }
        }
    }

    // ---- epilogue ----
    const float i0 = 1.f / l0, i1 = 1.f / l1;
    const size_t row0 = base + (size_t)(qt * 64 + w16 + g) * EMB;
    const size_t row1 = base + (size_t)(qt * 64 + w16 + g + 8) * EMB;
#pragma unroll
    for (int nt = 0; nt < 8; nt++) {
        const int c = nt * 8 + t * 2;
        *reinterpret_cast<float2*>(&out[row0 + c]) =
            make_float2(o[nt][0] * i0, o[nt][1] * i0);
        *reinterpret_cast<float2*>(&out[row1 + c]) =
            make_float2(o[nt][2] * i1, o[nt][3] * i1);
    }
}

// ---------------- logits + GAN loss -----------------------------------------
__global__ void loss_kernel(const float* __restrict__ xfin,
                            const float* __restrict__ wlr,
                            const float* __restrict__ blr,
                            float* __restrict__ out)
{
    __shared__ float slog[4];
    const int warp = threadIdx.x >> 5, lane = threadIdx.x & 31;
    if (warp < 4) {
        const float* xr = xfin + (size_t)warp * SEQ * EMB;  // token 0
        float s = 0.f;
        for (int i = lane; i < EMB; i += 32) s = fmaf(xr[i], wlr[i], s);
#pragma unroll
        for (int off = 16; off; off >>= 1)
            s += __shfl_xor_sync(0xffffffffu, s, off);
        if (lane == 0) slog[warp] = s + blr[0];
    }
    __syncthreads();
    if (threadIdx.x == 0) {
        auto sp = [](float t) {
            return fmaxf(t, 0.f) + log1pf(expf(-fabsf(t)));
        };
        float loss_real = 0.5f * (sp(-slog[0]) + sp(-slog[1]));
        float loss_fake = 0.5f * (sp( slog[2]) + sp( slog[3]));
        out[0] = 0.5f * (loss_fake + loss_real);
        out[1] = loss_fake;
    }
}

// ---------------- launch ----------------------------------------------------
extern "C" void kernel_launch(void* const* d_in, const int* in_sizes, int n_in,
                              void* d_out, int out_size)
{
    const float* x     = (const float*)d_in[0];
    const float* wq    = (const float*)d_in[1];
    const float* bq    = (const float*)d_in[2];
    const float* wk    = (const float*)d_in[3];
    const float* bk    = (const float*)d_in[4];
    const float* wv    = (const float*)d_in[5];
    const float* bv    = (const float*)d_in[6];
    const float* wo    = (const float*)d_in[7];
    const float* bo    = (const float*)d_in[8];
    const float* ln1_g = (const float*)d_in[9];
    const float* ln1_b = (const float*)d_in[10];
    const float* ln2_g = (const float*)d_in[11];
    const float* ln2_b = (const float*)d_in[12];
    const float* w1    = (const float*)d_in[13];
    const float* b1    = (const float*)d_in[14];
    const float* w2    = (const float*)d_in[15];
    const float* b2    = (const float*)d_in[16];
    const float* wlr   = (const float*)d_in[17];
    const float* blr   = (const float*)d_in[18];
    float* out = (float*)d_out;

    float *xn, *q, *k, *v, *att, *x1, *xn2, *ffn;
    cudaGetSymbolAddress((void**)&xn,  g_xn);
    cudaGetSymbolAddress((void**)&q,   g_q);
    cudaGetSymbolAddress((void**)&k,   g_k);
    cudaGetSymbolAddress((void**)&v,   g_v);
    cudaGetSymbolAddress((void**)&att, g_att);
    cudaGetSymbolAddress((void**)&x1,  g_x1);
    cudaGetSymbolAddress((void**)&xn2, g_xn2);
    cudaGetSymbolAddress((void**)&ffn, g_ffn);

    // 1) LN1
    ln_kernel<<<MROWS, 256>>>(x, ln1_g, ln1_b, xn);

    // 2) Q,K,V projections (fused, tf32 tensor cores)
    dim3 gQKV(EMB / 128, MROWS / 128, 3);
    gemm_qkv_kernel<<<gQKV, 256>>>(xn, wq, wk, wv, bq, bk, bv, q, k, v);

    // 3) attention (tf32 tensor cores)
    dim3 gAttn(SEQ / 64, NH, NB);
    attn_mma_kernel<<<gAttn, 128>>>(q, k, v, att);

    // 4) out-proj + residual -> x1
    dim3 gProj(EMB / 128, MROWS / 128);
    gemm_tf32_kernel<false, true><<<gProj, 256>>>(att, wo, bo, x, x1, MROWS, EMB, EMB);

    // 5) LN2
    ln_kernel<<<MROWS, 256>>>(x1, ln2_g, ln2_b, xn2);

    // 6) FFN1 with ReLU
    dim3 gFF1(FF / 128, MROWS / 128);
    gemm_tf32_kernel<true, false><<<gFF1, 256>>>(xn2, w1, b1, nullptr, ffn, MROWS, FF, EMB);

    // 7) FFN2 + residual -> final x (directly into d_out)
    gemm_tf32_kernel<false, true><<<gProj, 256>>>(ffn, w2, b2, x1, out, MROWS, EMB, FF);

    // 8) logits + losses
    loss_kernel<<<1, 128>>>(out, wlr, blr, out + X_SIZE);
}

// round 8
// speedup vs baseline: 5.8870x; 1.2695x over previous
#include <cuda_runtime.h>
#include <cuda_fp16.h>
#include <math.h>
#include <stdint.h>

// Problem dims (fixed by reference)
#define NB 4
#define SEQ 2048
#define EMB 1024
#define NH 16
#define HD 64
#define FF 4096
#define MROWS (NB * SEQ)          // 8192
#define X_SIZE (NB * SEQ * EMB)   // 8388608

// ---------------- scratch (device globals; no allocation allowed) ----------
__device__ float g_xn [MROWS * EMB];
__device__ float g_q  [MROWS * EMB];
__device__ float g_k  [MROWS * EMB];
__device__ float g_v  [MROWS * EMB];
__device__ float g_att[MROWS * EMB];
__device__ float g_x1 [MROWS * EMB];
__device__ float g_xn2[MROWS * EMB];
__device__ float g_ffn[MROWS * FF];
// transposed fp16 weights [N][K]
__device__ __half g_wtq[EMB * EMB];
__device__ __half g_wtk[EMB * EMB];
__device__ __half g_wtv[EMB * EMB];
__device__ __half g_wto[EMB * EMB];
__device__ __half g_wt1[FF * EMB];
__device__ __half g_wt2[EMB * FF];

// ---------------- helpers ---------------------------------------------------
__device__ __forceinline__ uint32_t h2u(__half2 h) {
    uint32_t u;
    u = *reinterpret_cast<uint32_t*>(&h);
    return u;
}

__device__ __forceinline__ uint32_t pack_h2(float lo, float hi) {
    return h2u(__floats2half2_rn(lo, hi));
}

__device__ __forceinline__ float tf32r(float x) {
    uint32_t u;
    asm("cvt.rna.tf32.f32 %0, %1;" : "=r"(u) : "f"(x));
    return __uint_as_float(u);
}

__device__ __forceinline__ uint32_t s2u(const void* p) {
    uint32_t a;
    asm("{ .reg .u64 t; cvta.to.shared.u64 t, %1; cvt.u32.u64 %0, t; }"
        : "=r"(a) : "l"(p));
    return a;
}

__device__ __forceinline__ void ldm_x4(uint32_t r[4], uint32_t addr) {
    asm volatile("ldmatrix.sync.aligned.m8n8.x4.shared.b16 {%0,%1,%2,%3}, [%4];"
                 : "=r"(r[0]), "=r"(r[1]), "=r"(r[2]), "=r"(r[3])
                 : "r"(addr));
}

__device__ __forceinline__ void mma_f16(float d[4], const uint32_t a[4],
                                        const uint32_t b0, const uint32_t b1) {
    asm volatile(
        "mma.sync.aligned.m16n8k16.row.col.f32.f16.f16.f32 "
        "{%0,%1,%2,%3},{%4,%5,%6,%7},{%8,%9},{%0,%1,%2,%3};"
        : "+f"(d[0]), "+f"(d[1]), "+f"(d[2]), "+f"(d[3])
        : "r"(a[0]), "r"(a[1]), "r"(a[2]), "r"(a[3]), "r"(b0), "r"(b1));
}

// legacy tf32 mma for attention
__device__ __forceinline__ void mma_tf32(float d[4],
                                         uint32_t a0, uint32_t a1,
                                         uint32_t a2, uint32_t a3,
                                         uint32_t b0, uint32_t b1) {
    asm volatile(
        "mma.sync.aligned.m16n8k8.row.col.f32.tf32.tf32.f32 "
        "{%0,%1,%2,%3}, {%4,%5,%6,%7}, {%8,%9}, {%0,%1,%2,%3};"
        : "+f"(d[0]), "+f"(d[1]), "+f"(d[2]), "+f"(d[3])
        : "r"(a0), "r"(a1), "r"(a2), "r"(a3), "r"(b0), "r"(b1));
}

// ---------------- weight transpose + fp16 convert: out[C][R] = in[R][C] -----
__global__ __launch_bounds__(256) void transpose_h_kernel(
    const float* __restrict__ in, __half* __restrict__ out, int R, int C)
{
    __shared__ float t[32][33];
    const int bc = blockIdx.x * 32, br = blockIdx.y * 32;
    const int x = threadIdx.x, y0 = threadIdx.y;
#pragma unroll
    for (int y = y0; y < 32; y += 8)
        t[y][x] = in[(size_t)(br + y) * C + bc + x];
    __syncthreads();
#pragma unroll
    for (int y = y0; y < 32; y += 8)
        out[(size_t)(bc + y) * R + br + x] = __float2half(t[x][y]);
}

// ---------------- layernorm --------------------------------------------------
__global__ __launch_bounds__(256) void ln_kernel(
    const float* __restrict__ in, const float* __restrict__ g,
    const float* __restrict__ b, float* __restrict__ out)
{
    const int row = blockIdx.x;
    const float* xr = in + (size_t)row * EMB;
    float* orow = out + (size_t)row * EMB;
    const int tid = threadIdx.x;

    float vals[4];
    float s = 0.f, sq = 0.f;
#pragma unroll
    for (int i = 0; i < 4; i++) {
        float v = xr[i * 256 + tid];
        vals[i] = v; s += v; sq += v * v;
    }
    __shared__ float red[16];
#pragma unroll
    for (int off = 16; off; off >>= 1) {
        s  += __shfl_xor_sync(0xffffffffu, s,  off);
        sq += __shfl_xor_sync(0xffffffffu, sq, off);
    }
    const int warp = tid >> 5, lane = tid & 31;
    if (lane == 0) { red[warp] = s; red[warp + 8] = sq; }
    __syncthreads();
    if (warp == 0) {
        float ss = (lane < 8) ? red[lane] : 0.f;
        float qq = (lane < 8) ? red[lane + 8] : 0.f;
#pragma unroll
        for (int off = 4; off; off >>= 1) {
            ss += __shfl_xor_sync(0xffffffffu, ss, off);
            qq += __shfl_xor_sync(0xffffffffu, qq, off);
        }
        if (lane == 0) { red[0] = ss; red[1] = qq; }
    }
    __syncthreads();
    const float mean = red[0] * (1.0f / EMB);
    const float var  = red[1] * (1.0f / EMB) - mean * mean;
    const float inv  = rsqrtf(var + 1e-5f);
#pragma unroll
    for (int i = 0; i < 4; i++) {
        int idx = i * 256 + tid;
        orow[idx] = (vals[i] - mean) * inv * g[idx] + b[idx];
    }
}

// ---------------- fp16 tensor-core GEMM --------------------------------------
// C[M,N] = act(A[M,K] @ BT[N,K]^T + bias [+ res]).
// Block tile 128x128, k-step 16, 256 thr (8 warps), warp tile 64x32.
// Smem: rows padded to 48B (24 halves) -> conflict-free ldmatrix (3i mod 8 perm).
#define STG 3072   // halves per stage buffer (128 rows * 24)

template <bool RELU, bool RES>
__device__ __forceinline__ void gemm_h_body(
    const float* __restrict__ A, const __half* __restrict__ BT,
    const float* __restrict__ bias, const float* __restrict__ res,
    float* __restrict__ C, int M, int N, int K, int bx, int by)
{
    __shared__ __half sA[2 * STG];
    __shared__ __half sB[2 * STG];

    const int tid = threadIdx.x;
    const int warpId = tid >> 5, lane = tid & 31;
    const int t = lane & 3, g = lane >> 2;
    const int wr = warpId & 1;          // 0..1 : 64-row group
    const int wc = warpId >> 1;         // 0..3 : 32-col group
    const int rowStart = by * 128;
    const int colStart = bx * 128;
    const int KT = K / 16;

    // stage-loader mapping: thread -> (row 0..127, k-half 0..1)
    const int srow = tid >> 1, skh = tid & 1;
    const float* Ap = A  + (size_t)(rowStart + srow) * K + skh * 8;
    const __half* Bp = BT + (size_t)(colStart + srow) * K + skh * 8;
    __half* sAdst = &sA[srow * 24 + skh * 8];
    __half* sBdst = &sB[srow * 24 + skh * 8];

    // ldmatrix base addresses (per-lane)
    const uint32_t aBase = s2u(sA) +
        (uint32_t)((wr * 64 + (lane & 15)) * 48 + (lane >> 4) * 16);
    const uint32_t bBase = s2u(sB) +
        (uint32_t)((wc * 32 + ((lane >> 4) << 3) + (lane & 7)) * 48 +
                   ((lane >> 3) & 1) * 16);

    float acc[4][4][4];
#pragma unroll
    for (int mt = 0; mt < 4; mt++)
#pragma unroll
        for (int nt = 0; nt < 4; nt++)
#pragma unroll
            for (int r = 0; r < 4; r++) acc[mt][nt][r] = 0.f;

    // prologue: stage 0
    {
        float4 a0 = *reinterpret_cast<const float4*>(Ap);
        float4 a1 = *reinterpret_cast<const float4*>(Ap + 4);
        uint4 ua = make_uint4(pack_h2(a0.x, a0.y), pack_h2(a0.z, a0.w),
                              pack_h2(a1.x, a1.y), pack_h2(a1.z, a1.w));
        *reinterpret_cast<uint4*>(sAdst) = ua;
        *reinterpret_cast<uint4*>(sBdst) =
            *reinterpret_cast<const uint4*>(Bp);
    }
    __syncthreads();

    int buf = 0;
    for (int kt = 1; kt <= KT; kt++) {
        const bool more = (kt < KT);
        float4 pa0, pa1; uint4 pb;
        if (more) {
            pa0 = *reinterpret_cast<const float4*>(Ap + kt * 16);
            pa1 = *reinterpret_cast<const float4*>(Ap + kt * 16 + 4);
            pb  = *reinterpret_cast<const uint4*>(Bp + kt * 16);
        }

        // ---- compute on buf ----
        {
            const uint32_t aOff = aBase + buf * (STG * 2);
            const uint32_t bOff = bBase + buf * (STG * 2);
            uint32_t af[4][4];
#pragma unroll
            for (int mt = 0; mt < 4; mt++)
                ldm_x4(af[mt], aOff + mt * 768);
            uint32_t bf0[4], bf1[4];
            ldm_x4(bf0, bOff);          // n-tiles 0,1
            ldm_x4(bf1, bOff + 768);    // n-tiles 2,3
#pragma unroll
            for (int mt = 0; mt < 4; mt++) {
                mma_f16(acc[mt][0], af[mt], bf0[0], bf0[1]);
                mma_f16(acc[mt][1], af[mt], bf0[2], bf0[3]);
                mma_f16(acc[mt][2], af[mt], bf1[0], bf1[1]);
                mma_f16(acc[mt][3], af[mt], bf1[2], bf1[3]);
            }
        }

        if (more) {
            const int nb = buf ^ 1;
            uint4 ua = make_uint4(pack_h2(pa0.x, pa0.y), pack_h2(pa0.z, pa0.w),
                                  pack_h2(pa1.x, pa1.y), pack_h2(pa1.z, pa1.w));
            *reinterpret_cast<uint4*>(sAdst + nb * STG) = ua;
            *reinterpret_cast<uint4*>(sBdst + nb * STG) = pb;
            __syncthreads();
            buf = nb;
        }
    }

    // ---- epilogue (m16n8 fragment layout) ----
#pragma unroll
    for (int mt = 0; mt < 4; mt++) {
        const int r0 = rowStart + wr * 64 + mt * 16 + g;
#pragma unroll
        for (int nt = 0; nt < 4; nt++) {
            const int c0 = colStart + wc * 32 + nt * 8 + t * 2;
            float bx0 = bias[c0], by0 = bias[c0 + 1];
            float v0 = acc[mt][nt][0] + bx0;
            float v1 = acc[mt][nt][1] + by0;
            float v2 = acc[mt][nt][2] + bx0;
            float v3 = acc[mt][nt][3] + by0;
            const size_t off0 = (size_t)r0 * N + c0;
            const size_t off1 = (size_t)(r0 + 8) * N + c0;
            if (RES) {
                float2 q0 = *reinterpret_cast<const float2*>(&res[off0]);
                float2 q1 = *reinterpret_cast<const float2*>(&res[off1]);
                v0 += q0.x; v1 += q0.y; v2 += q1.x; v3 += q1.y;
            }
            if (RELU) {
                v0 = fmaxf(v0, 0.f); v1 = fmaxf(v1, 0.f);
                v2 = fmaxf(v2, 0.f); v3 = fmaxf(v3, 0.f);
            }
            *reinterpret_cast<float2*>(&C[off0]) = make_float2(v0, v1);
            *reinterpret_cast<float2*>(&C[off1]) = make_float2(v2, v3);
        }
    }
}

template <bool RELU, bool RES>
__global__ __launch_bounds__(256, 2) void gemm_h_kernel(
    const float* __restrict__ A, const __half* __restrict__ BT,
    const float* __restrict__ bias, const float* __restrict__ res,
    float* __restrict__ C, int M, int N, int K)
{
    gemm_h_body<RELU, RES>(A, BT, bias, res, C, M, N, K,
                           blockIdx.x, blockIdx.y);
}

__global__ __launch_bounds__(256, 2) void gemm_h_qkv_kernel(
    const float* __restrict__ A,
    const __half* __restrict__ wt0, const __half* __restrict__ wt1,
    const __half* __restrict__ wt2,
    const float* __restrict__ b0, const float* __restrict__ b1,
    const float* __restrict__ b2,
    float* __restrict__ c0, float* __restrict__ c1, float* __restrict__ c2)
{
    const int z = blockIdx.z;
    const __half* BT  = (z == 0) ? wt0 : (z == 1) ? wt1 : wt2;
    const float* bias = (z == 0) ? b0  : (z == 1) ? b1  : b2;
    float* C          = (z == 0) ? c0  : (z == 1) ? c1  : c2;
    gemm_h_body<false, false>(A, BT, bias, nullptr, C, MROWS, EMB, EMB,
                              blockIdx.x, blockIdx.y);
}

// ---------------- flash attention (legacy tf32 MMA) -------------------------
__global__ __launch_bounds__(128, 3) void attn_mma_kernel(
    const float* __restrict__ q, const float* __restrict__ k,
    const float* __restrict__ v, float* __restrict__ out)
{
    __shared__ float KV[64][68];
    __shared__ float Ps[64][68];

    const int qt = blockIdx.x, h = blockIdx.y, n = blockIdx.z;
    const int tid = threadIdx.x;
    const int warp = tid >> 5, lane = tid & 31;
    const int g = lane >> 2, t = lane & 3;
    const int w16 = warp * 16;
    const size_t base = ((size_t)n * SEQ) * EMB + h * HD;

#pragma unroll
    for (int it = 0; it < 8; it++) {
        const int u = tid + it * 128;
        const int rr = u >> 4, d4 = (u & 15) * 4;
        float4 tq = *reinterpret_cast<const float4*>(
            &q[base + (size_t)(qt * 64 + rr) * EMB + d4]);
        *reinterpret_cast<float4*>(&KV[rr][d4]) =
            make_float4(tf32r(tq.x * 0.125f), tf32r(tq.y * 0.125f),
                        tf32r(tq.z * 0.125f), tf32r(tq.w * 0.125f));
    }
    __syncthreads();

    uint32_t qf[8][4];
#pragma unroll
    for (int k8 = 0; k8 < 8; k8++) {
        qf[k8][0] = __float_as_uint(KV[w16 + g    ][k8 * 8 + t    ]);
        qf[k8][1] = __float_as_uint(KV[w16 + g + 8][k8 * 8 + t    ]);
        qf[k8][2] = __float_as_uint(KV[w16 + g    ][k8 * 8 + t + 4]);
        qf[k8][3] = __float_as_uint(KV[w16 + g + 8][k8 * 8 + t + 4]);
    }

    float m0 = -INFINITY, m1 = -INFINITY, l0 = 0.f, l1 = 0.f;
    float o[8][4];
#pragma unroll
    for (int nt = 0; nt < 8; nt++)
#pragma unroll
        for (int r = 0; r < 4; r++) o[nt][r] = 0.f;

    for (int kt = 0; kt < SEQ / 64; kt++) {
        __syncthreads();
#pragma unroll
        for (int it = 0; it < 8; it++) {
            const int u = tid + it * 128;
            const int cc = u >> 4, d4 = (u & 15) * 4;
            float4 tk = *reinterpret_cast<const float4*>(
                &k[base + (size_t)(kt * 64 + cc) * EMB + d4]);
            *reinterpret_cast<float4*>(&KV[cc][d4]) =
                make_float4(tf32r(tk.x), tf32r(tk.y), tf32r(tk.z), tf32r(tk.w));
        }
        __syncthreads();

        float s[8][4];
#pragma unroll
        for (int nt = 0; nt < 8; nt++)
#pragma unroll
            for (int r = 0; r < 4; r++) s[nt][r] = 0.f;

#pragma unroll
        for (int k8 = 0; k8 < 8; k8++) {
#pragma unroll
            for (int nt = 0; nt < 8; nt++) {
                const int c = nt * 8 + g;
                uint32_t b0 = __float_as_uint(KV[c][k8 * 8 + t    ]);
                uint32_t b1 = __float_as_uint(KV[c][k8 * 8 + t + 4]);
                mma_tf32(s[nt], qf[k8][0], qf[k8][1], qf[k8][2], qf[k8][3],
                         b0, b1);
            }
        }

        float mt0 = -INFINITY, mt1 = -INFINITY;
#pragma unroll
        for (int nt = 0; nt < 8; nt++) {
            mt0 = fmaxf(mt0, fmaxf(s[nt][0], s[nt][1]));
            mt1 = fmaxf(mt1, fmaxf(s[nt][2], s[nt][3]));
        }
        mt0 = fmaxf(mt0, __shfl_xor_sync(0xffffffffu, mt0, 1));
        mt0 = fmaxf(mt0, __shfl_xor_sync(0xffffffffu, mt0, 2));
        mt1 = fmaxf(mt1, __shfl_xor_sync(0xffffffffu, mt1, 1));
        mt1 = fmaxf(mt1, __shfl_xor_sync(0xffffffffu, mt1, 2));

        const float mn0 = fmaxf(m0, mt0), mn1 = fmaxf(m1, mt1);
        const float c0 = __expf(m0 - mn0), c1 = __expf(m1 - mn1);
        float ls0 = 0.f, ls1 = 0.f;
#pragma unroll
        for (int nt = 0; nt < 8; nt++) {
            const float p0 = __expf(s[nt][0] - mn0);
            const float p1 = __expf(s[nt][1] - mn0);
            const float p2 = __expf(s[nt][2] - mn1);
            const float p3 = __expf(s[nt][3] - mn1);
            ls0 += p0 + p1; ls1 += p2 + p3;
            *reinterpret_cast<float2*>(&Ps[w16 + g    ][nt * 8 + t * 2]) =
                make_float2(tf32r(p0), tf32r(p1));
            *reinterpret_cast<float2*>(&Ps[w16 + g + 8][nt * 8 + t * 2]) =
                make_float2(tf32r(p2), tf32r(p3));
        }
        ls0 += __shfl_xor_sync(0xffffffffu, ls0, 1);
        ls0 += __shfl_xor_sync(0xffffffffu, ls0, 2);
        ls1 += __shfl_xor_sync(0xffffffffu, ls1, 1);
        ls1 += __shfl_xor_sync(0xffffffffu, ls1, 2);
        l0 = l0 * c0 + ls0; l1 = l1 * c1 + ls1;
        m0 = mn0; m1 = mn1;
#pragma unroll
        for (int nt = 0; nt < 8; nt++) {
            o[nt][0] *= c0; o[nt][1] *= c0;
            o[nt][2] *= c1; o[nt][3] *= c1;
        }
        __syncthreads();

#pragma unroll
        for (int it = 0; it < 8; it++) {
            const int u = tid + it * 128;
            const int cc = u >> 4, d4 = (u & 15) * 4;
            float4 tv = *reinterpret_cast<const float4*>(
                &v[base + (size_t)(kt * 64 + cc) * EMB + d4]);
            *reinterpret_cast<float4*>(&KV[cc][d4]) =
                make_float4(tf32r(tv.x), tf32r(tv.y), tf32r(tv.z), tf32r(tv.w));
        }
        __syncthreads();

#pragma unroll
        for (int k8 = 0; k8 < 8; k8++) {
            uint32_t a0 = __float_as_uint(Ps[w16 + g    ][k8 * 8 + t    ]);
            uint32_t a1 = __float_as_uint(Ps[w16 + g + 8][k8 * 8 + t    ]);
            uint32_t a2 = __float_as_uint(Ps[w16 + g    ][k8 * 8 + t + 4]);
            uint32_t a3 = __float_as_uint(Ps[w16 + g + 8][k8 * 8 + t + 4]);
#pragma unroll
            for (int nt = 0; nt < 8; nt++) {
                uint32_t b0 = __float_as_uint(KV[k8 * 8 + t    ][nt * 8 + g]);
                uint32_t b1 = __float_as_uint(KV[k8 * 8 + t + 4][nt * 8 + g]);
                mma_tf32(o[nt], a0, a1, a2, a3, b0, b1);
            }
        }
    }

    const float i0 = 1.f / l0, i1 = 1.f / l1;
    const size_t row0 = base + (size_t)(qt * 64 + w16 + g) * EMB;
    const size_t row1 = base + (size_t)(qt * 64 + w16 + g + 8) * EMB;
#pragma unroll
    for (int nt = 0; nt < 8; nt++) {
        const int c = nt * 8 + t * 2;
        *reinterpret_cast<float2*>(&out[row0 + c]) =
            make_float2(o[nt][0] * i0, o[nt][1] * i0);
        *reinterpret_cast<float2*>(&out[row1 + c]) =
            make_float2(o[nt][2] * i1, o[nt][3] * i1);
    }
}

// ---------------- logits + GAN loss -----------------------------------------
__global__ void loss_kernel(const float* __restrict__ xfin,
                            const float* __restrict__ wlr,
                            const float* __restrict__ blr,
                            float* __restrict__ out)
{
    __shared__ float slog[4];
    const int warp = threadIdx.x >> 5, lane = threadIdx.x & 31;
    if (warp < 4) {
        const float* xr = xfin + (size_t)warp * SEQ * EMB;  // token 0
        float s = 0.f;
        for (int i = lane; i < EMB; i += 32) s = fmaf(xr[i], wlr[i], s);
#pragma unroll
        for (int off = 16; off; off >>= 1)
            s += __shfl_xor_sync(0xffffffffu, s, off);
        if (lane == 0) slog[warp] = s + blr[0];
    }
    __syncthreads();
    if (threadIdx.x == 0) {
        auto sp = [](float t) {
            return fmaxf(t, 0.f) + log1pf(expf(-fabsf(t)));
        };
        float loss_real = 0.5f * (sp(-slog[0]) + sp(-slog[1]));
        float loss_fake = 0.5f * (sp( slog[2]) + sp( slog[3]));
        out[0] = 0.5f * (loss_fake + loss_real);
        out[1] = loss_fake;
    }
}

// ---------------- launch ----------------------------------------------------
extern "C" void kernel_launch(void* const* d_in, const int* in_sizes, int n_in,
                              void* d_out, int out_size)
{
    const float* x     = (const float*)d_in[0];
    const float* wq    = (const float*)d_in[1];
    const float* bq    = (const float*)d_in[2];
    const float* wk    = (const float*)d_in[3];
    const float* bk    = (const float*)d_in[4];
    const float* wv    = (const float*)d_in[5];
    const float* bv    = (const float*)d_in[6];
    const float* wo    = (const float*)d_in[7];
    const float* bo    = (const float*)d_in[8];
    const float* ln1_g = (const float*)d_in[9];
    const float* ln1_b = (const float*)d_in[10];
    const float* ln2_g = (const float*)d_in[11];
    const float* ln2_b = (const float*)d_in[12];
    const float* w1    = (const float*)d_in[13];
    const float* b1    = (const float*)d_in[14];
    const float* w2    = (const float*)d_in[15];
    const float* b2    = (const float*)d_in[16];
    const float* wlr   = (const float*)d_in[17];
    const float* blr   = (const float*)d_in[18];
    float* out = (float*)d_out;

    float *xn, *q, *k, *v, *att, *x1, *xn2, *ffn;
    __half *wtq, *wtk, *wtv, *wto, *wt1, *wt2;
    cudaGetSymbolAddress((void**)&xn,  g_xn);
    cudaGetSymbolAddress((void**)&q,   g_q);
    cudaGetSymbolAddress((void**)&k,   g_k);
    cudaGetSymbolAddress((void**)&v,   g_v);
    cudaGetSymbolAddress((void**)&att, g_att);
    cudaGetSymbolAddress((void**)&x1,  g_x1);
    cudaGetSymbolAddress((void**)&xn2, g_xn2);
    cudaGetSymbolAddress((void**)&ffn, g_ffn);
    cudaGetSymbolAddress((void**)&wtq, g_wtq);
    cudaGetSymbolAddress((void**)&wtk, g_wtk);
    cudaGetSymbolAddress((void**)&wtv, g_wtv);
    cudaGetSymbolAddress((void**)&wto, g_wto);
    cudaGetSymbolAddress((void**)&wt1, g_wt1);
    cudaGetSymbolAddress((void**)&wt2, g_wt2);

    // 0) weight transposes + fp16 convert (once per call; deterministic)
    dim3 tb(32, 8);
    transpose_h_kernel<<<dim3(EMB / 32, EMB / 32), tb>>>(wq, wtq, EMB, EMB);
    transpose_h_kernel<<<dim3(EMB / 32, EMB / 32), tb>>>(wk, wtk, EMB, EMB);
    transpose_h_kernel<<<dim3(EMB / 32, EMB / 32), tb>>>(wv, wtv, EMB, EMB);
    transpose_h_kernel<<<dim3(EMB / 32, EMB / 32), tb>>>(wo, wto, EMB, EMB);
    transpose_h_kernel<<<dim3(FF / 32,  EMB / 32), tb>>>(w1, wt1, EMB, FF);
    transpose_h_kernel<<<dim3(EMB / 32, FF / 32),  tb>>>(w2, wt2, FF, EMB);

    // 1) LN1
    ln_kernel<<<MROWS, 256>>>(x, ln1_g, ln1_b, xn);

    // 2) QKV projections (fp16 mma, fused via grid.z)
    dim3 gQKV(EMB / 128, MROWS / 128, 3);
    gemm_h_qkv_kernel<<<gQKV, 256>>>(xn, wtq, wtk, wtv, bq, bk, bv, q, k, v);

    // 3) attention (legacy tf32 mma)
    dim3 gAttn(SEQ / 64, NH, NB);
    attn_mma_kernel<<<gAttn, 128>>>(q, k, v, att);

    // 4) out-proj + residual -> x1
    dim3 gProj(EMB / 128, MROWS / 128);
    gemm_h_kernel<false, true><<<gProj, 256>>>(att, wto, bo, x, x1,
                                               MROWS, EMB, EMB);

    // 5) LN2
    ln_kernel<<<MROWS, 256>>>(x1, ln2_g, ln2_b, xn2);

    // 6) FFN1 with ReLU
    dim3 gFF1(FF / 128, MROWS / 128);
    gemm_h_kernel<true, false><<<gFF1, 256>>>(xn2, wt1, b1, nullptr, ffn,
                                              MROWS, FF, EMB);

    // 7) FFN2 + residual -> final x (into d_out)
    gemm_h_kernel<false, true><<<gProj, 256>>>(ffn, wt2, b2, x1, out,
                                               MROWS, EMB, FF);

    // 8) logits + losses
    loss_kernel<<<1, 128>>>(out, wlr, blr, out + X_SIZE);
}

// round 9
// speedup vs baseline: 8.5868x; 1.4586x over previous
#include <cuda_runtime.h>
#include <cuda_fp16.h>
#include <math.h>
#include <stdint.h>

// Problem dims (fixed by reference)
#define NB 4
#define SEQ 2048
#define EMB 1024
#define NH 16
#define HD 64
#define FF 4096
#define MROWS (NB * SEQ)          // 8192
#define X_SIZE (NB * SEQ * EMB)   // 8388608

// ---------------- scratch (device globals; no allocation allowed) ----------
__device__ __half g_xn [MROWS * EMB];
__device__ __half g_q  [MROWS * EMB];
__device__ __half g_k  [MROWS * EMB];
__device__ __half g_v  [MROWS * EMB];
__device__ __half g_att[MROWS * EMB];
__device__ float  g_x1 [MROWS * EMB];
__device__ __half g_xn2[MROWS * EMB];
__device__ __half g_ffn[MROWS * FF];
// transposed fp16 weights [N][K]
__device__ __half g_wtq[EMB * EMB];
__device__ __half g_wtk[EMB * EMB];
__device__ __half g_wtv[EMB * EMB];
__device__ __half g_wto[EMB * EMB];
__device__ __half g_wt1[FF * EMB];
__device__ __half g_wt2[EMB * FF];

// ---------------- helpers ---------------------------------------------------
__device__ __forceinline__ uint32_t h2u(__half2 h) {
    return *reinterpret_cast<uint32_t*>(&h);
}
__device__ __forceinline__ uint32_t pack_h2(float lo, float hi) {
    return h2u(__floats2half2_rn(lo, hi));
}

__device__ __forceinline__ uint32_t s2u(const void* p) {
    uint32_t a;
    asm("{ .reg .u64 t; cvta.to.shared.u64 t, %1; cvt.u32.u64 %0, t; }"
        : "=r"(a) : "l"(p));
    return a;
}

__device__ __forceinline__ void ldm_x4(uint32_t r[4], uint32_t addr) {
    asm volatile("ldmatrix.sync.aligned.m8n8.x4.shared.b16 {%0,%1,%2,%3}, [%4];"
                 : "=r"(r[0]), "=r"(r[1]), "=r"(r[2]), "=r"(r[3])
                 : "r"(addr));
}
__device__ __forceinline__ void ldm_x4_t(uint32_t r[4], uint32_t addr) {
    asm volatile("ldmatrix.sync.aligned.m8n8.x4.trans.shared.b16 {%0,%1,%2,%3}, [%4];"
                 : "=r"(r[0]), "=r"(r[1]), "=r"(r[2]), "=r"(r[3])
                 : "r"(addr));
}

__device__ __forceinline__ void mma_f16(float d[4], const uint32_t a[4],
                                        const uint32_t b0, const uint32_t b1) {
    asm volatile(
        "mma.sync.aligned.m16n8k16.row.col.f32.f16.f16.f32 "
        "{%0,%1,%2,%3},{%4,%5,%6,%7},{%8,%9},{%0,%1,%2,%3};"
        : "+f"(d[0]), "+f"(d[1]), "+f"(d[2]), "+f"(d[3])
        : "r"(a[0]), "r"(a[1]), "r"(a[2]), "r"(a[3]), "r"(b0), "r"(b1));
}

// typed pair-store (fp32 or fp16 destination)
__device__ __forceinline__ void store2(float* p, float a, float b) {
    *reinterpret_cast<float2*>(p) = make_float2(a, b);
}
__device__ __forceinline__ void store2(__half* p, float a, float b) {
    *reinterpret_cast<uint32_t*>(p) = pack_h2(a, b);
}

// ---------------- weight transpose + fp16 convert: out[C][R] = in[R][C] -----
__global__ __launch_bounds__(256) void transpose_h_kernel(
    const float* __restrict__ in, __half* __restrict__ out, int R, int C)
{
    __shared__ float t[32][33];
    const int bc = blockIdx.x * 32, br = blockIdx.y * 32;
    const int x = threadIdx.x, y0 = threadIdx.y;
#pragma unroll
    for (int y = y0; y < 32; y += 8)
        t[y][x] = in[(size_t)(br + y) * C + bc + x];
    __syncthreads();
#pragma unroll
    for (int y = y0; y < 32; y += 8)
        out[(size_t)(bc + y) * R + br + x] = __float2half(t[x][y]);
}

// ---------------- layernorm (fp32 in, fp16 out) -----------------------------
__global__ __launch_bounds__(256) void ln_kernel(
    const float* __restrict__ in, const float* __restrict__ g,
    const float* __restrict__ b, __half* __restrict__ out)
{
    const int row = blockIdx.x;
    const float* xr = in + (size_t)row * EMB;
    __half* orow = out + (size_t)row * EMB;
    const int tid = threadIdx.x;

    float vals[4];
    float s = 0.f, sq = 0.f;
#pragma unroll
    for (int i = 0; i < 4; i++) {
        float v = xr[i * 256 + tid];
        vals[i] = v; s += v; sq += v * v;
    }
    __shared__ float red[16];
#pragma unroll
    for (int off = 16; off; off >>= 1) {
        s  += __shfl_xor_sync(0xffffffffu, s,  off);
        sq += __shfl_xor_sync(0xffffffffu, sq, off);
    }
    const int warp = tid >> 5, lane = tid & 31;
    if (lane == 0) { red[warp] = s; red[warp + 8] = sq; }
    __syncthreads();
    if (warp == 0) {
        float ss = (lane < 8) ? red[lane] : 0.f;
        float qq = (lane < 8) ? red[lane + 8] : 0.f;
#pragma unroll
        for (int off = 4; off; off >>= 1) {
            ss += __shfl_xor_sync(0xffffffffu, ss, off);
            qq += __shfl_xor_sync(0xffffffffu, qq, off);
        }
        if (lane == 0) { red[0] = ss; red[1] = qq; }
    }
    __syncthreads();
    const float mean = red[0] * (1.0f / EMB);
    const float var  = red[1] * (1.0f / EMB) - mean * mean;
    const float inv  = rsqrtf(var + 1e-5f);
#pragma unroll
    for (int i = 0; i < 4; i++) {
        int idx = i * 256 + tid;
        orow[idx] = __float2half((vals[i] - mean) * inv * g[idx] + b[idx]);
    }
}

// ---------------- fp16 tensor-core GEMM --------------------------------------
// C[M,N] = act(A[M,K] @ BT[N,K]^T + bias [+ res]).  A fp16, BT fp16.
// Block tile 128x128, k-step 16, 256 thr (8 warps), warp tile 64x32.
#define STG 3072   // halves per stage buffer (128 rows * 24)

template <typename TOut, bool RELU, bool RES>
__device__ __forceinline__ void gemm_h_body(
    const __half* __restrict__ A, const __half* __restrict__ BT,
    const float* __restrict__ bias, const float* __restrict__ res,
    TOut* __restrict__ C, int M, int N, int K, int bx, int by)
{
    __shared__ __half sA[2 * STG];
    __shared__ __half sB[2 * STG];

    const int tid = threadIdx.x;
    const int warpId = tid >> 5, lane = tid & 31;
    const int t = lane & 3, g = lane >> 2;
    const int wr = warpId & 1;
    const int wc = warpId >> 1;
    const int rowStart = by * 128;
    const int colStart = bx * 128;
    const int KT = K / 16;

    const int srow = tid >> 1, skh = tid & 1;
    const __half* Ap = A  + (size_t)(rowStart + srow) * K + skh * 8;
    const __half* Bp = BT + (size_t)(colStart + srow) * K + skh * 8;
    __half* sAdst = &sA[srow * 24 + skh * 8];
    __half* sBdst = &sB[srow * 24 + skh * 8];

    const uint32_t aBase = s2u(sA) +
        (uint32_t)((wr * 64 + (lane & 15)) * 48 + (lane >> 4) * 16);
    const uint32_t bBase = s2u(sB) +
        (uint32_t)((wc * 32 + ((lane >> 4) << 3) + (lane & 7)) * 48 +
                   ((lane >> 3) & 1) * 16);

    float acc[4][4][4];
#pragma unroll
    for (int mt = 0; mt < 4; mt++)
#pragma unroll
        for (int nt = 0; nt < 4; nt++)
#pragma unroll
            for (int r = 0; r < 4; r++) acc[mt][nt][r] = 0.f;

    // prologue: stage 0
    *reinterpret_cast<uint4*>(sAdst) = *reinterpret_cast<const uint4*>(Ap);
    *reinterpret_cast<uint4*>(sBdst) = *reinterpret_cast<const uint4*>(Bp);
    __syncthreads();

    int buf = 0;
    for (int kt = 1; kt <= KT; kt++) {
        const bool more = (kt < KT);
        uint4 pa, pb;
        if (more) {
            pa = *reinterpret_cast<const uint4*>(Ap + kt * 16);
            pb = *reinterpret_cast<const uint4*>(Bp + kt * 16);
        }

        {
            const uint32_t aOff = aBase + buf * (STG * 2);
            const uint32_t bOff = bBase + buf * (STG * 2);
            uint32_t af[4][4];
#pragma unroll
            for (int mt = 0; mt < 4; mt++)
                ldm_x4(af[mt], aOff + mt * 768);
            uint32_t bf0[4], bf1[4];
            ldm_x4(bf0, bOff);
            ldm_x4(bf1, bOff + 768);
#pragma unroll
            for (int mt = 0; mt < 4; mt++) {
                mma_f16(acc[mt][0], af[mt], bf0[0], bf0[1]);
                mma_f16(acc[mt][1], af[mt], bf0[2], bf0[3]);
                mma_f16(acc[mt][2], af[mt], bf1[0], bf1[1]);
                mma_f16(acc[mt][3], af[mt], bf1[2], bf1[3]);
            }
        }

        if (more) {
            const int nb = buf ^ 1;
            *reinterpret_cast<uint4*>(sAdst + nb * STG) = pa;
            *reinterpret_cast<uint4*>(sBdst + nb * STG) = pb;
            __syncthreads();
            buf = nb;
        }
    }

    // ---- epilogue ----
#pragma unroll
    for (int mt = 0; mt < 4; mt++) {
        const int r0 = rowStart + wr * 64 + mt * 16 + g;
#pragma unroll
        for (int nt = 0; nt < 4; nt++) {
            const int c0 = colStart + wc * 32 + nt * 8 + t * 2;
            float bx0 = bias[c0], by0 = bias[c0 + 1];
            float v0 = acc[mt][nt][0] + bx0;
            float v1 = acc[mt][nt][1] + by0;
            float v2 = acc[mt][nt][2] + bx0;
            float v3 = acc[mt][nt][3] + by0;
            const size_t off0 = (size_t)r0 * N + c0;
            const size_t off1 = (size_t)(r0 + 8) * N + c0;
            if (RES) {
                float2 q0 = *reinterpret_cast<const float2*>(&res[off0]);
                float2 q1 = *reinterpret_cast<const float2*>(&res[off1]);
                v0 += q0.x; v1 += q0.y; v2 += q1.x; v3 += q1.y;
            }
            if (RELU) {
                v0 = fmaxf(v0, 0.f); v1 = fmaxf(v1, 0.f);
                v2 = fmaxf(v2, 0.f); v3 = fmaxf(v3, 0.f);
            }
            store2(&C[off0], v0, v1);
            store2(&C[off1], v2, v3);
        }
    }
}

template <typename TOut, bool RELU, bool RES>
__global__ __launch_bounds__(256, 2) void gemm_h_kernel(
    const __half* __restrict__ A, const __half* __restrict__ BT,
    const float* __restrict__ bias, const float* __restrict__ res,
    TOut* __restrict__ C, int M, int N, int K)
{
    gemm_h_body<TOut, RELU, RES>(A, BT, bias, res, C, M, N, K,
                                 blockIdx.x, blockIdx.y);
}

__global__ __launch_bounds__(256, 2) void gemm_h_qkv_kernel(
    const __half* __restrict__ A,
    const __half* __restrict__ wt0, const __half* __restrict__ wt1,
    const __half* __restrict__ wt2,
    const float* __restrict__ b0, const float* __restrict__ b1,
    const float* __restrict__ b2,
    __half* __restrict__ c0, __half* __restrict__ c1, __half* __restrict__ c2)
{
    const int z = blockIdx.z;
    const __half* BT  = (z == 0) ? wt0 : (z == 1) ? wt1 : wt2;
    const float* bias = (z == 0) ? b0  : (z == 1) ? b1  : b2;
    __half* C         = (z == 0) ? c0  : (z == 1) ? c1  : c2;
    gemm_h_body<__half, false, false>(A, BT, bias, nullptr, C,
                                      MROWS, EMB, EMB, blockIdx.x, blockIdx.y);
}

// ---------------- flash attention (fp16 m16n8k16) ---------------------------
// q,k,v,out: fp16 [NB, SEQ, EMB], head h at cols h*64..h*64+63.
// grid (SEQ/64, NH, NB); 128 threads (4 warps), warp = 16 query rows.
// Smem pitch 72 halves (144B = 9 x 16B groups -> conflict-free ldmatrix).
#define AP 72

__global__ __launch_bounds__(128) void attn_h_kernel(
    const __half* __restrict__ q, const __half* __restrict__ k,
    const __half* __restrict__ v, __half* __restrict__ out)
{
    __shared__ __half Ks[64 * AP];
    __shared__ __half Vs[64 * AP];
    __shared__ __half Ps[64 * AP];

    const int qt = blockIdx.x, h = blockIdx.y, n = blockIdx.z;
    const int tid = threadIdx.x;
    const int warp = tid >> 5, lane = tid & 31;
    const int g = lane >> 2, t = lane & 3;
    const int w16 = warp * 16;
    const size_t base = ((size_t)n * SEQ) * EMB + h * HD;

    const uint32_t ksB = s2u(Ks), vsB = s2u(Vs), psB = s2u(Ps);

    // stage Q into Ks, build register fragments (4 k-steps)
#pragma unroll
    for (int it = 0; it < 4; it++) {
        const int u = tid + it * 128;
        const int rr = u >> 3, c8 = (u & 7) * 8;
        *reinterpret_cast<uint4*>(&Ks[rr * AP + c8]) =
            *reinterpret_cast<const uint4*>(
                &q[base + (size_t)(qt * 64 + rr) * EMB + c8]);
    }
    __syncthreads();

    uint32_t qf[4][4];
#pragma unroll
    for (int ks = 0; ks < 4; ks++)
        ldm_x4(qf[ks], ksB + (uint32_t)(((w16 + (lane & 15)) * AP +
                                         ks * 16 + ((lane >> 4) * 8)) * 2));

    float m0 = -INFINITY, m1 = -INFINITY, l0 = 0.f, l1 = 0.f;
    float o[8][4];
#pragma unroll
    for (int nt = 0; nt < 8; nt++)
#pragma unroll
        for (int r = 0; r < 4; r++) o[nt][r] = 0.f;

    for (int kt = 0; kt < SEQ / 64; kt++) {
        __syncthreads();   // qf built / prev iter done with Ks,Vs
        // ---- load K and V tiles ----
#pragma unroll
        for (int it = 0; it < 4; it++) {
            const int u = tid + it * 128;
            const int rr = u >> 3, c8 = (u & 7) * 8;
            const size_t gsrc = base + (size_t)(kt * 64 + rr) * EMB + c8;
            *reinterpret_cast<uint4*>(&Ks[rr * AP + c8]) =
                *reinterpret_cast<const uint4*>(&k[gsrc]);
            *reinterpret_cast<uint4*>(&Vs[rr * AP + c8]) =
                *reinterpret_cast<const uint4*>(&v[gsrc]);
        }
        __syncthreads();

        // ---- S = Q K^T ----
        float s[8][4];
#pragma unroll
        for (int nt = 0; nt < 8; nt++)
#pragma unroll
            for (int r = 0; r < 4; r++) s[nt][r] = 0.f;

#pragma unroll
        for (int ks = 0; ks < 4; ks++) {
#pragma unroll
            for (int j = 0; j < 4; j++) {
                uint32_t bf[4];
                ldm_x4(bf, ksB + (uint32_t)(((j * 16 + ((lane >> 4) << 3) +
                                              (lane & 7)) * AP + ks * 16 +
                                             ((lane >> 3) & 1) * 8) * 2));
                mma_f16(s[2 * j],     qf[ks], bf[0], bf[1]);
                mma_f16(s[2 * j + 1], qf[ks], bf[2], bf[3]);
            }
        }

        // ---- online softmax (scale 1/8 applied here) ----
#pragma unroll
        for (int nt = 0; nt < 8; nt++)
#pragma unroll
            for (int r = 0; r < 4; r++) s[nt][r] *= 0.125f;

        float mt0 = -INFINITY, mt1 = -INFINITY;
#pragma unroll
        for (int nt = 0; nt < 8; nt++) {
            mt0 = fmaxf(mt0, fmaxf(s[nt][0], s[nt][1]));
            mt1 = fmaxf(mt1, fmaxf(s[nt][2], s[nt][3]));
        }
        mt0 = fmaxf(mt0, __shfl_xor_sync(0xffffffffu, mt0, 1));
        mt0 = fmaxf(mt0, __shfl_xor_sync(0xffffffffu, mt0, 2));
        mt1 = fmaxf(mt1, __shfl_xor_sync(0xffffffffu, mt1, 1));
        mt1 = fmaxf(mt1, __shfl_xor_sync(0xffffffffu, mt1, 2));

        const float mn0 = fmaxf(m0, mt0), mn1 = fmaxf(m1, mt1);
        const float c0 = __expf(m0 - mn0), c1 = __expf(m1 - mn1);
        float ls0 = 0.f, ls1 = 0.f;
#pragma unroll
        for (int nt = 0; nt < 8; nt++) {
            const float p0 = __expf(s[nt][0] - mn0);
            const float p1 = __expf(s[nt][1] - mn0);
            const float p2 = __expf(s[nt][2] - mn1);
            const float p3 = __expf(s[nt][3] - mn1);
            ls0 += p0 + p1; ls1 += p2 + p3;
            *reinterpret_cast<uint32_t*>(
                &Ps[(w16 + g) * AP + nt * 8 + t * 2]) = pack_h2(p0, p1);
            *reinterpret_cast<uint32_t*>(
                &Ps[(w16 + g + 8) * AP + nt * 8 + t * 2]) = pack_h2(p2, p3);
        }
        ls0 += __shfl_xor_sync(0xffffffffu, ls0, 1);
        ls0 += __shfl_xor_sync(0xffffffffu, ls0, 2);
        ls1 += __shfl_xor_sync(0xffffffffu, ls1, 1);
        ls1 += __shfl_xor_sync(0xffffffffu, ls1, 2);
        l0 = l0 * c0 + ls0; l1 = l1 * c1 + ls1;
        m0 = mn0; m1 = mn1;
#pragma unroll
        for (int nt = 0; nt < 8; nt++) {
            o[nt][0] *= c0; o[nt][1] *= c0;
            o[nt][2] *= c1; o[nt][3] *= c1;
        }
        __syncwarp();   // Ps rows of this warp visible to its own ldmatrix

        // ---- O += P V  (A = Ps non-trans, B = Vs trans) ----
#pragma unroll
        for (int ks = 0; ks < 4; ks++) {
            uint32_t pf[4];
            ldm_x4(pf, psB + (uint32_t)(((w16 + (lane & 15)) * AP + ks * 16 +
                                         ((lane >> 4) * 8)) * 2));
#pragma unroll
            for (int j = 0; j < 4; j++) {
                uint32_t vf[4];
                const int row = ks * 16 + (lane & 7) + ((lane >> 3) & 1) * 8;
                ldm_x4_t(vf, vsB + (uint32_t)((row * AP + j * 16 +
                                               (lane >> 4) * 8) * 2));
                mma_f16(o[2 * j],     pf, vf[0], vf[1]);
                mma_f16(o[2 * j + 1], pf, vf[2], vf[3]);
            }
        }
    }

    // ---- epilogue (fp16 out) ----
    const float i0 = 1.f / l0, i1 = 1.f / l1;
    const size_t row0 = base + (size_t)(qt * 64 + w16 + g) * EMB;
    const size_t row1 = base + (size_t)(qt * 64 + w16 + g + 8) * EMB;
#pragma unroll
    for (int nt = 0; nt < 8; nt++) {
        const int c = nt * 8 + t * 2;
        *reinterpret_cast<uint32_t*>(&out[row0 + c]) =
            pack_h2(o[nt][0] * i0, o[nt][1] * i0);
        *reinterpret_cast<uint32_t*>(&out[row1 + c]) =
            pack_h2(o[nt][2] * i1, o[nt][3] * i1);
    }
}

// ---------------- logits + GAN loss -----------------------------------------
__global__ void loss_kernel(const float* __restrict__ xfin,
                            const float* __restrict__ wlr,
                            const float* __restrict__ blr,
                            float* __restrict__ out)
{
    __shared__ float slog[4];
    const int warp = threadIdx.x >> 5, lane = threadIdx.x & 31;
    if (warp < 4) {
        const float* xr = xfin + (size_t)warp * SEQ * EMB;  // token 0
        float s = 0.f;
        for (int i = lane; i < EMB; i += 32) s = fmaf(xr[i], wlr[i], s);
#pragma unroll
        for (int off = 16; off; off >>= 1)
            s += __shfl_xor_sync(0xffffffffu, s, off);
        if (lane == 0) slog[warp] = s + blr[0];
    }
    __syncthreads();
    if (threadIdx.x == 0) {
        auto sp = [](float t) {
            return fmaxf(t, 0.f) + log1pf(expf(-fabsf(t)));
        };
        float loss_real = 0.5f * (sp(-slog[0]) + sp(-slog[1]));
        float loss_fake = 0.5f * (sp( slog[2]) + sp( slog[3]));
        out[0] = 0.5f * (loss_fake + loss_real);
        out[1] = loss_fake;
    }
}

// ---------------- launch ----------------------------------------------------
extern "C" void kernel_launch(void* const* d_in, const int* in_sizes, int n_in,
                              void* d_out, int out_size)
{
    const float* x     = (const float*)d_in[0];
    const float* wq    = (const float*)d_in[1];
    const float* bq    = (const float*)d_in[2];
    const float* wk    = (const float*)d_in[3];
    const float* bk    = (const float*)d_in[4];
    const float* wv    = (const float*)d_in[5];
    const float* bv    = (const float*)d_in[6];
    const float* wo    = (const float*)d_in[7];
    const float* bo    = (const float*)d_in[8];
    const float* ln1_g = (const float*)d_in[9];
    const float* ln1_b = (const float*)d_in[10];
    const float* ln2_g = (const float*)d_in[11];
    const float* ln2_b = (const float*)d_in[12];
    const float* w1    = (const float*)d_in[13];
    const float* b1    = (const float*)d_in[14];
    const float* w2    = (const float*)d_in[15];
    const float* b2    = (const float*)d_in[16];
    const float* wlr   = (const float*)d_in[17];
    const float* blr   = (const float*)d_in[18];
    float* out = (float*)d_out;

    __half *xn, *qh, *kh, *vh, *att, *xn2, *ffn;
    float* x1;
    __half *wtq, *wtk, *wtv, *wto, *wt1, *wt2;
    cudaGetSymbolAddress((void**)&xn,  g_xn);
    cudaGetSymbolAddress((void**)&qh,  g_q);
    cudaGetSymbolAddress((void**)&kh,  g_k);
    cudaGetSymbolAddress((void**)&vh,  g_v);
    cudaGetSymbolAddress((void**)&att, g_att);
    cudaGetSymbolAddress((void**)&x1,  g_x1);
    cudaGetSymbolAddress((void**)&xn2, g_xn2);
    cudaGetSymbolAddress((void**)&ffn, g_ffn);
    cudaGetSymbolAddress((void**)&wtq, g_wtq);
    cudaGetSymbolAddress((void**)&wtk, g_wtk);
    cudaGetSymbolAddress((void**)&wtv, g_wtv);
    cudaGetSymbolAddress((void**)&wto, g_wto);
    cudaGetSymbolAddress((void**)&wt1, g_wt1);
    cudaGetSymbolAddress((void**)&wt2, g_wt2);

    // 0) weight transposes + fp16 convert
    dim3 tb(32, 8);
    transpose_h_kernel<<<dim3(EMB / 32, EMB / 32), tb>>>(wq, wtq, EMB, EMB);
    transpose_h_kernel<<<dim3(EMB / 32, EMB / 32), tb>>>(wk, wtk, EMB, EMB);
    transpose_h_kernel<<<dim3(EMB / 32, EMB / 32), tb>>>(wv, wtv, EMB, EMB);
    transpose_h_kernel<<<dim3(EMB / 32, EMB / 32), tb>>>(wo, wto, EMB, EMB);
    transpose_h_kernel<<<dim3(FF / 32,  EMB / 32), tb>>>(w1, wt1, EMB, FF);
    transpose_h_kernel<<<dim3(EMB / 32, FF / 32),  tb>>>(w2, wt2, FF, EMB);

    // 1) LN1 -> fp16
    ln_kernel<<<MROWS, 256>>>(x, ln1_g, ln1_b, xn);

    // 2) QKV projections -> fp16 q,k,v
    dim3 gQKV(EMB / 128, MROWS / 128, 3);
    gemm_h_qkv_kernel<<<gQKV, 256>>>(xn, wtq, wtk, wtv, bq, bk, bv,
                                     qh, kh, vh);

    // 3) attention (fp16 mma) -> fp16 att
    dim3 gAttn(SEQ / 64, NH, NB);
    attn_h_kernel<<<gAttn, 128>>>(qh, kh, vh, att);

    // 4) out-proj + residual(x fp32) -> x1 fp32
    dim3 gProj(EMB / 128, MROWS / 128);
    gemm_h_kernel<float, false, true><<<gProj, 256>>>(
        att, wto, bo, x, x1, MROWS, EMB, EMB);

    // 5) LN2 -> fp16
    ln_kernel<<<MROWS, 256>>>(x1, ln2_g, ln2_b, xn2);

    // 6) FFN1 + ReLU -> fp16 ffn
    dim3 gFF1(FF / 128, MROWS / 128);
    gemm_h_kernel<__half, true, false><<<gFF1, 256>>>(
        xn2, wt1, b1, nullptr, ffn, MROWS, FF, EMB);

    // 7) FFN2 + residual(x1 fp32) -> final fp32 out
    gemm_h_kernel<float, false, true><<<gProj, 256>>>(
        ffn, wt2, b2, x1, out, MROWS, EMB, FF);

    // 8) logits + losses
    loss_kernel<<<1, 128>>>(out, wlr, blr, out + X_SIZE);
}

// round 10
// speedup vs baseline: 10.2331x; 1.1917x over previous
#include <cuda_runtime.h>
#include <cuda_fp16.h>
#include <math.h>
#include <stdint.h>

// Problem dims (fixed by reference)
#define NB 4
#define SEQ 2048
#define EMB 1024
#define NH 16
#define HD 64
#define FF 4096
#define MROWS (NB * SEQ)          // 8192
#define X_SIZE (NB * SEQ * EMB)   // 8388608

// ---------------- scratch (device globals; no allocation allowed) ----------
__device__ __half g_xn [MROWS * EMB];
__device__ __half g_q  [MROWS * EMB];
__device__ __half g_k  [MROWS * EMB];
__device__ __half g_v  [MROWS * EMB];
__device__ __half g_att[MROWS * EMB];
__device__ float  g_x1 [MROWS * EMB];
__device__ __half g_xn2[MROWS * EMB];
__device__ __half g_ffn[MROWS * FF];
// transposed fp16 weights [N][K]
__device__ __half g_wtq[EMB * EMB];
__device__ __half g_wtk[EMB * EMB];
__device__ __half g_wtv[EMB * EMB];
__device__ __half g_wto[EMB * EMB];
__device__ __half g_wt1[FF * EMB];
__device__ __half g_wt2[EMB * FF];

// ---------------- helpers ---------------------------------------------------
__device__ __forceinline__ uint32_t h2u(__half2 h) {
    return *reinterpret_cast<uint32_t*>(&h);
}
__device__ __forceinline__ uint32_t pack_h2(float lo, float hi) {
    return h2u(__floats2half2_rn(lo, hi));
}

__device__ __forceinline__ uint32_t s2u(const void* p) {
    uint32_t a;
    asm("{ .reg .u64 t; cvta.to.shared.u64 t, %1; cvt.u32.u64 %0, t; }"
        : "=r"(a) : "l"(p));
    return a;
}

__device__ __forceinline__ void cp16(uint32_t dst, const void* src) {
    asm volatile("cp.async.cg.shared.global [%0], [%1], 16;"
                 :: "r"(dst), "l"(src));
}
#define CP_COMMIT() asm volatile("cp.async.commit_group;" ::: "memory")
#define CP_WAIT1()  asm volatile("cp.async.wait_group 1;" ::: "memory")

__device__ __forceinline__ void ldm_x4(uint32_t r[4], uint32_t addr) {
    asm volatile("ldmatrix.sync.aligned.m8n8.x4.shared.b16 {%0,%1,%2,%3}, [%4];"
                 : "=r"(r[0]), "=r"(r[1]), "=r"(r[2]), "=r"(r[3])
                 : "r"(addr));
}
__device__ __forceinline__ void ldm_x4_t(uint32_t r[4], uint32_t addr) {
    asm volatile("ldmatrix.sync.aligned.m8n8.x4.trans.shared.b16 {%0,%1,%2,%3}, [%4];"
                 : "=r"(r[0]), "=r"(r[1]), "=r"(r[2]), "=r"(r[3])
                 : "r"(addr));
}

__device__ __forceinline__ void mma_f16(float d[4], const uint32_t a[4],
                                        const uint32_t b0, const uint32_t b1) {
    asm volatile(
        "mma.sync.aligned.m16n8k16.row.col.f32.f16.f16.f32 "
        "{%0,%1,%2,%3},{%4,%5,%6,%7},{%8,%9},{%0,%1,%2,%3};"
        : "+f"(d[0]), "+f"(d[1]), "+f"(d[2]), "+f"(d[3])
        : "r"(a[0]), "r"(a[1]), "r"(a[2]), "r"(a[3]), "r"(b0), "r"(b1));
}

// typed pair-store (fp32 or fp16 destination)
__device__ __forceinline__ void store2(float* p, float a, float b) {
    *reinterpret_cast<float2*>(p) = make_float2(a, b);
}
__device__ __forceinline__ void store2(__half* p, float a, float b) {
    *reinterpret_cast<uint32_t*>(p) = pack_h2(a, b);
}

// ---------------- weight transpose + fp16 convert: out[C][R] = in[R][C] -----
__global__ __launch_bounds__(256) void transpose_h_kernel(
    const float* __restrict__ in, __half* __restrict__ out, int R, int C)
{
    __shared__ float t[32][33];
    const int bc = blockIdx.x * 32, br = blockIdx.y * 32;
    const int x = threadIdx.x, y0 = threadIdx.y;
#pragma unroll
    for (int y = y0; y < 32; y += 8)
        t[y][x] = in[(size_t)(br + y) * C + bc + x];
    __syncthreads();
#pragma unroll
    for (int y = y0; y < 32; y += 8)
        out[(size_t)(bc + y) * R + br + x] = __float2half(t[x][y]);
}

// ---------------- layernorm (fp32 in, fp16 out) -----------------------------
__global__ __launch_bounds__(256) void ln_kernel(
    const float* __restrict__ in, const float* __restrict__ g,
    const float* __restrict__ b, __half* __restrict__ out)
{
    const int row = blockIdx.x;
    const float* xr = in + (size_t)row * EMB;
    __half* orow = out + (size_t)row * EMB;
    const int tid = threadIdx.x;

    float vals[4];
    float s = 0.f, sq = 0.f;
#pragma unroll
    for (int i = 0; i < 4; i++) {
        float v = xr[i * 256 + tid];
        vals[i] = v; s += v; sq += v * v;
    }
    __shared__ float red[16];
#pragma unroll
    for (int off = 16; off; off >>= 1) {
        s  += __shfl_xor_sync(0xffffffffu, s,  off);
        sq += __shfl_xor_sync(0xffffffffu, sq, off);
    }
    const int warp = tid >> 5, lane = tid & 31;
    if (lane == 0) { red[warp] = s; red[warp + 8] = sq; }
    __syncthreads();
    if (warp == 0) {
        float ss = (lane < 8) ? red[lane] : 0.f;
        float qq = (lane < 8) ? red[lane + 8] : 0.f;
#pragma unroll
        for (int off = 4; off; off >>= 1) {
            ss += __shfl_xor_sync(0xffffffffu, ss, off);
            qq += __shfl_xor_sync(0xffffffffu, qq, off);
        }
        if (lane == 0) { red[0] = ss; red[1] = qq; }
    }
    __syncthreads();
    const float mean = red[0] * (1.0f / EMB);
    const float var  = red[1] * (1.0f / EMB) - mean * mean;
    const float inv  = rsqrtf(var + 1e-5f);
#pragma unroll
    for (int i = 0; i < 4; i++) {
        int idx = i * 256 + tid;
        orow[idx] = __float2half((vals[i] - mean) * inv * g[idx] + b[idx]);
    }
}

// ---------------- fp16 tensor-core GEMM (cp.async 3-stage) -------------------
// C[M,N] = act(A[M,K] @ BT[N,K]^T + bias [+ res]).
// Block tile 128x128, k-step 16, 256 thr (8 warps), warp tile 64x32.
// Smem rows padded to 48B (24 halves) -> conflict-free ldmatrix.
#define STG 3072   // halves per stage buffer (128 rows * 24)
#define NSTAGE 3

template <typename TOut, bool RELU, bool RES>
__device__ __forceinline__ void gemm_h_body(
    const __half* __restrict__ A, const __half* __restrict__ BT,
    const float* __restrict__ bias, const float* __restrict__ res,
    TOut* __restrict__ C, int M, int N, int K, int bx, int by)
{
    __shared__ __half sA[NSTAGE * STG];
    __shared__ __half sB[NSTAGE * STG];

    const int tid = threadIdx.x;
    const int warpId = tid >> 5, lane = tid & 31;
    const int t = lane & 3, g = lane >> 2;
    const int wr = warpId & 1;
    const int wc = warpId >> 1;
    const int rowStart = by * 128;
    const int colStart = bx * 128;
    const int KT = K / 16;

    // stage-loader mapping: thread -> (row 0..127, k-half 0..1), 16B each
    const int srow = tid >> 1, skh = tid & 1;
    const __half* Ap = A  + (size_t)(rowStart + srow) * K + skh * 8;
    const __half* Bp = BT + (size_t)(colStart + srow) * K + skh * 8;
    const uint32_t sAu = s2u(sA) + (uint32_t)((srow * 24 + skh * 8) * 2);
    const uint32_t sBu = s2u(sB) + (uint32_t)((srow * 24 + skh * 8) * 2);

    // ldmatrix base addresses (per-lane)
    const uint32_t aBase = s2u(sA) +
        (uint32_t)((wr * 64 + (lane & 15)) * 48 + (lane >> 4) * 16);
    const uint32_t bBase = s2u(sB) +
        (uint32_t)((wc * 32 + ((lane >> 4) << 3) + (lane & 7)) * 48 +
                   ((lane >> 3) & 1) * 16);

    float acc[4][4][4];
#pragma unroll
    for (int mt = 0; mt < 4; mt++)
#pragma unroll
        for (int nt = 0; nt < 4; nt++)
#pragma unroll
            for (int r = 0; r < 4; r++) acc[mt][nt][r] = 0.f;

    // prologue: issue stages 0 and 1
    cp16(sAu, Ap);
    cp16(sBu, Bp);
    CP_COMMIT();
    cp16(sAu + STG * 2, Ap + 16);
    cp16(sBu + STG * 2, Bp + 16);
    CP_COMMIT();

    int buf = 0;
    for (int kt = 0; kt < KT; kt++) {
        CP_WAIT1();            // stage kt landed (<=1 group pending)
        __syncthreads();       // visible to all; prev compute on buf done

        // issue stage kt+2 into buffer (kt+2)%3 (= (kt-1)%3, retired above)
        if (kt + 2 < KT) {
            const int nb = (buf + 2 >= NSTAGE) ? buf + 2 - NSTAGE : buf + 2;
            cp16(sAu + nb * (STG * 2), Ap + (kt + 2) * 16);
            cp16(sBu + nb * (STG * 2), Bp + (kt + 2) * 16);
        }
        CP_COMMIT();           // keep group count in lockstep

        // ---- compute on buf ----
        {
            const uint32_t aOff = aBase + buf * (STG * 2);
            const uint32_t bOff = bBase + buf * (STG * 2);
            uint32_t af[4][4];
#pragma unroll
            for (int mt = 0; mt < 4; mt++)
                ldm_x4(af[mt], aOff + mt * 768);
            uint32_t bf0[4], bf1[4];
            ldm_x4(bf0, bOff);
            ldm_x4(bf1, bOff + 768);
#pragma unroll
            for (int mt = 0; mt < 4; mt++) {
                mma_f16(acc[mt][0], af[mt], bf0[0], bf0[1]);
                mma_f16(acc[mt][1], af[mt], bf0[2], bf0[3]);
                mma_f16(acc[mt][2], af[mt], bf1[0], bf1[1]);
                mma_f16(acc[mt][3], af[mt], bf1[2], bf1[3]);
            }
        }
        buf = (buf + 1 >= NSTAGE) ? 0 : buf + 1;
        __syncthreads();       // all warps done with buf before overwrite
    }

    // ---- epilogue ----
#pragma unroll
    for (int mt = 0; mt < 4; mt++) {
        const int r0 = rowStart + wr * 64 + mt * 16 + g;
#pragma unroll
        for (int nt = 0; nt < 4; nt++) {
            const int c0 = colStart + wc * 32 + nt * 8 + t * 2;
            float bx0 = bias[c0], by0 = bias[c0 + 1];
            float v0 = acc[mt][nt][0] + bx0;
            float v1 = acc[mt][nt][1] + by0;
            float v2 = acc[mt][nt][2] + bx0;
            float v3 = acc[mt][nt][3] + by0;
            const size_t off0 = (size_t)r0 * N + c0;
            const size_t off1 = (size_t)(r0 + 8) * N + c0;
            if (RES) {
                float2 q0 = *reinterpret_cast<const float2*>(&res[off0]);
                float2 q1 = *reinterpret_cast<const float2*>(&res[off1]);
                v0 += q0.x; v1 += q0.y; v2 += q1.x; v3 += q1.y;
            }
            if (RELU) {
                v0 = fmaxf(v0, 0.f); v1 = fmaxf(v1, 0.f);
                v2 = fmaxf(v2, 0.f); v3 = fmaxf(v3, 0.f);
            }
            store2(&C[off0], v0, v1);
            store2(&C[off1], v2, v3);
        }
    }
}

template <typename TOut, bool RELU, bool RES>
__global__ __launch_bounds__(256, 2) void gemm_h_kernel(
    const __half* __restrict__ A, const __half* __restrict__ BT,
    const float* __restrict__ bias, const float* __restrict__ res,
    TOut* __restrict__ C, int M, int N, int K)
{
    gemm_h_body<TOut, RELU, RES>(A, BT, bias, res, C, M, N, K,
                                 blockIdx.x, blockIdx.y);
}

__global__ __launch_bounds__(256, 2) void gemm_h_qkv_kernel(
    const __half* __restrict__ A,
    const __half* __restrict__ wt0, const __half* __restrict__ wt1,
    const __half* __restrict__ wt2,
    const float* __restrict__ b0, const float* __restrict__ b1,
    const float* __restrict__ b2,
    __half* __restrict__ c0, __half* __restrict__ c1, __half* __restrict__ c2)
{
    const int z = blockIdx.z;
    const __half* BT  = (z == 0) ? wt0 : (z == 1) ? wt1 : wt2;
    const float* bias = (z == 0) ? b0  : (z == 1) ? b1  : b2;
    __half* C         = (z == 0) ? c0  : (z == 1) ? c1  : c2;
    gemm_h_body<__half, false, false>(A, BT, bias, nullptr, C,
                                      MROWS, EMB, EMB, blockIdx.x, blockIdx.y);
}

// ---------------- flash attention (fp16 m16n8k16) ---------------------------
#define AP 72

__global__ __launch_bounds__(128) void attn_h_kernel(
    const __half* __restrict__ q, const __half* __restrict__ k,
    const __half* __restrict__ v, __half* __restrict__ out)
{
    __shared__ __half Ks[64 * AP];
    __shared__ __half Vs[64 * AP];
    __shared__ __half Ps[64 * AP];

    const int qt = blockIdx.x, h = blockIdx.y, n = blockIdx.z;
    const int tid = threadIdx.x;
    const int warp = tid >> 5, lane = tid & 31;
    const int g = lane >> 2, t = lane & 3;
    const int w16 = warp * 16;
    const size_t base = ((size_t)n * SEQ) * EMB + h * HD;

    const uint32_t ksB = s2u(Ks), vsB = s2u(Vs), psB = s2u(Ps);

    // stage Q into Ks, build register fragments
#pragma unroll
    for (int it = 0; it < 4; it++) {
        const int u = tid + it * 128;
        const int rr = u >> 3, c8 = (u & 7) * 8;
        *reinterpret_cast<uint4*>(&Ks[rr * AP + c8]) =
            *reinterpret_cast<const uint4*>(
                &q[base + (size_t)(qt * 64 + rr) * EMB + c8]);
    }
    __syncthreads();

    uint32_t qf[4][4];
#pragma unroll
    for (int ks = 0; ks < 4; ks++)
        ldm_x4(qf[ks], ksB + (uint32_t)(((w16 + (lane & 15)) * AP +
                                         ks * 16 + ((lane >> 4) * 8)) * 2));

    float m0 = -INFINITY, m1 = -INFINITY, l0 = 0.f, l1 = 0.f;
    float o[8][4];
#pragma unroll
    for (int nt = 0; nt < 8; nt++)
#pragma unroll
        for (int r = 0; r < 4; r++) o[nt][r] = 0.f;

    for (int kt = 0; kt < SEQ / 64; kt++) {
        __syncthreads();
#pragma unroll
        for (int it = 0; it < 4; it++) {
            const int u = tid + it * 128;
            const int rr = u >> 3, c8 = (u & 7) * 8;
            const size_t gsrc = base + (size_t)(kt * 64 + rr) * EMB + c8;
            *reinterpret_cast<uint4*>(&Ks[rr * AP + c8]) =
                *reinterpret_cast<const uint4*>(&k[gsrc]);
            *reinterpret_cast<uint4*>(&Vs[rr * AP + c8]) =
                *reinterpret_cast<const uint4*>(&v[gsrc]);
        }
        __syncthreads();

        float s[8][4];
#pragma unroll
        for (int nt = 0; nt < 8; nt++)
#pragma unroll
            for (int r = 0; r < 4; r++) s[nt][r] = 0.f;

#pragma unroll
        for (int ks = 0; ks < 4; ks++) {
#pragma unroll
            for (int j = 0; j < 4; j++) {
                uint32_t bf[4];
                ldm_x4(bf, ksB + (uint32_t)(((j * 16 + ((lane >> 4) << 3) +
                                              (lane & 7)) * AP + ks * 16 +
                                             ((lane >> 3) & 1) * 8) * 2));
                mma_f16(s[2 * j],     qf[ks], bf[0], bf[1]);
                mma_f16(s[2 * j + 1], qf[ks], bf[2], bf[3]);
            }
        }

#pragma unroll
        for (int nt = 0; nt < 8; nt++)
#pragma unroll
            for (int r = 0; r < 4; r++) s[nt][r] *= 0.125f;

        float mt0 = -INFINITY, mt1 = -INFINITY;
#pragma unroll
        for (int nt = 0; nt < 8; nt++) {
            mt0 = fmaxf(mt0, fmaxf(s[nt][0], s[nt][1]));
            mt1 = fmaxf(mt1, fmaxf(s[nt][2], s[nt][3]));
        }
        mt0 = fmaxf(mt0, __shfl_xor_sync(0xffffffffu, mt0, 1));
        mt0 = fmaxf(mt0, __shfl_xor_sync(0xffffffffu, mt0, 2));
        mt1 = fmaxf(mt1, __shfl_xor_sync(0xffffffffu, mt1, 1));
        mt1 = fmaxf(mt1, __shfl_xor_sync(0xffffffffu, mt1, 2));

        const float mn0 = fmaxf(m0, mt0), mn1 = fmaxf(m1, mt1);
        const float c0 = __expf(m0 - mn0), c1 = __expf(m1 - mn1);
        float ls0 = 0.f, ls1 = 0.f;
#pragma unroll
        for (int nt = 0; nt < 8; nt++) {
            const float p0 = __expf(s[nt][0] - mn0);
            const float p1 = __expf(s[nt][1] - mn0);
            const float p2 = __expf(s[nt][2] - mn1);
            const float p3 = __expf(s[nt][3] - mn1);
            ls0 += p0 + p1; ls1 += p2 + p3;
            *reinterpret_cast<uint32_t*>(
                &Ps[(w16 + g) * AP + nt * 8 + t * 2]) = pack_h2(p0, p1);
            *reinterpret_cast<uint32_t*>(
                &Ps[(w16 + g + 8) * AP + nt * 8 + t * 2]) = pack_h2(p2, p3);
        }
        ls0 += __shfl_xor_sync(0xffffffffu, ls0, 1);
        ls0 += __shfl_xor_sync(0xffffffffu, ls0, 2);
        ls1 += __shfl_xor_sync(0xffffffffu, ls1, 1);
        ls1 += __shfl_xor_sync(0xffffffffu, ls1, 2);
        l0 = l0 * c0 + ls0; l1 = l1 * c1 + ls1;
        m0 = mn0; m1 = mn1;
#pragma unroll
        for (int nt = 0; nt < 8; nt++) {
            o[nt][0] *= c0; o[nt][1] *= c0;
            o[nt][2] *= c1; o[nt][3] *= c1;
        }
        __syncwarp();

#pragma unroll
        for (int ks = 0; ks < 4; ks++) {
            uint32_t pf[4];
            ldm_x4(pf, psB + (uint32_t)(((w16 + (lane & 15)) * AP + ks * 16 +
                                         ((lane >> 4) * 8)) * 2));
#pragma unroll
            for (int j = 0; j < 4; j++) {
                uint32_t vf[4];
                const int row = ks * 16 + (lane & 7) + ((lane >> 3) & 1) * 8;
                ldm_x4_t(vf, vsB + (uint32_t)((row * AP + j * 16 +
                                               (lane >> 4) * 8) * 2));
                mma_f16(o[2 * j],     pf, vf[0], vf[1]);
                mma_f16(o[2 * j + 1], pf, vf[2], vf[3]);
            }
        }
    }

    const float i0 = 1.f / l0, i1 = 1.f / l1;
    const size_t row0 = base + (size_t)(qt * 64 + w16 + g) * EMB;
    const size_t row1 = base + (size_t)(qt * 64 + w16 + g + 8) * EMB;
#pragma unroll
    for (int nt = 0; nt < 8; nt++) {
        const int c = nt * 8 + t * 2;
        *reinterpret_cast<uint32_t*>(&out[row0 + c]) =
            pack_h2(o[nt][0] * i0, o[nt][1] * i0);
        *reinterpret_cast<uint32_t*>(&out[row1 + c]) =
            pack_h2(o[nt][2] * i1, o[nt][3] * i1);
    }
}

// ---------------- logits + GAN loss -----------------------------------------
__global__ void loss_kernel(const float* __restrict__ xfin,
                            const float* __restrict__ wlr,
                            const float* __restrict__ blr,
                            float* __restrict__ out)
{
    __shared__ float slog[4];
    const int warp = threadIdx.x >> 5, lane = threadIdx.x & 31;
    if (warp < 4) {
        const float* xr = xfin + (size_t)warp * SEQ * EMB;  // token 0
        float s = 0.f;
        for (int i = lane; i < EMB; i += 32) s = fmaf(xr[i], wlr[i], s);
#pragma unroll
        for (int off = 16; off; off >>= 1)
            s += __shfl_xor_sync(0xffffffffu, s, off);
        if (lane == 0) slog[warp] = s + blr[0];
    }
    __syncthreads();
    if (threadIdx.x == 0) {
        auto sp = [](float t) {
            return fmaxf(t, 0.f) + log1pf(expf(-fabsf(t)));
        };
        float loss_real = 0.5f * (sp(-slog[0]) + sp(-slog[1]));
        float loss_fake = 0.5f * (sp( slog[2]) + sp( slog[3]));
        out[0] = 0.5f * (loss_fake + loss_real);
        out[1] = loss_fake;
    }
}

// ---------------- launch ----------------------------------------------------
extern "C" void kernel_launch(void* const* d_in, const int* in_sizes, int n_in,
                              void* d_out, int out_size)
{
    const float* x     = (const float*)d_in[0];
    const float* wq    = (const float*)d_in[1];
    const float* bq    = (const float*)d_in[2];
    const float* wk    = (const float*)d_in[3];
    const float* bk    = (const float*)d_in[4];
    const float* wv    = (const float*)d_in[5];
    const float* bv    = (const float*)d_in[6];
    const float* wo    = (const float*)d_in[7];
    const float* bo    = (const float*)d_in[8];
    const float* ln1_g = (const float*)d_in[9];
    const float* ln1_b = (const float*)d_in[10];
    const float* ln2_g = (const float*)d_in[11];
    const float* ln2_b = (const float*)d_in[12];
    const float* w1    = (const float*)d_in[13];
    const float* b1    = (const float*)d_in[14];
    const float* w2    = (const float*)d_in[15];
    const float* b2    = (const float*)d_in[16];
    const float* wlr   = (const float*)d_in[17];
    const float* blr   = (const float*)d_in[18];
    float* out = (float*)d_out;

    __half *xn, *qh, *kh, *vh, *att, *xn2, *ffn;
    float* x1;
    __half *wtq, *wtk, *wtv, *wto, *wt1, *wt2;
    cudaGetSymbolAddress((void**)&xn,  g_xn);
    cudaGetSymbolAddress((void**)&qh,  g_q);
    cudaGetSymbolAddress((void**)&kh,  g_k);
    cudaGetSymbolAddress((void**)&vh,  g_v);
    cudaGetSymbolAddress((void**)&att, g_att);
    cudaGetSymbolAddress((void**)&x1,  g_x1);
    cudaGetSymbolAddress((void**)&xn2, g_xn2);
    cudaGetSymbolAddress((void**)&ffn, g_ffn);
    cudaGetSymbolAddress((void**)&wtq, g_wtq);
    cudaGetSymbolAddress((void**)&wtk, g_wtk);
    cudaGetSymbolAddress((void**)&wtv, g_wtv);
    cudaGetSymbolAddress((void**)&wto, g_wto);
    cudaGetSymbolAddress((void**)&wt1, g_wt1);
    cudaGetSymbolAddress((void**)&wt2, g_wt2);

    // 0) weight transposes + fp16 convert
    dim3 tb(32, 8);
    transpose_h_kernel<<<dim3(EMB / 32, EMB / 32), tb>>>(wq, wtq, EMB, EMB);
    transpose_h_kernel<<<dim3(EMB / 32, EMB / 32), tb>>>(wk, wtk, EMB, EMB);
    transpose_h_kernel<<<dim3(EMB / 32, EMB / 32), tb>>>(wv, wtv, EMB, EMB);
    transpose_h_kernel<<<dim3(EMB / 32, EMB / 32), tb>>>(wo, wto, EMB, EMB);
    transpose_h_kernel<<<dim3(FF / 32,  EMB / 32), tb>>>(w1, wt1, EMB, FF);
    transpose_h_kernel<<<dim3(EMB / 32, FF / 32),  tb>>>(w2, wt2, FF, EMB);

    // 1) LN1 -> fp16
    ln_kernel<<<MROWS, 256>>>(x, ln1_g, ln1_b, xn);

    // 2) QKV projections -> fp16 q,k,v
    dim3 gQKV(EMB / 128, MROWS / 128, 3);
    gemm_h_qkv_kernel<<<gQKV, 256>>>(xn, wtq, wtk, wtv, bq, bk, bv,
                                     qh, kh, vh);

    // 3) attention (fp16 mma) -> fp16 att
    dim3 gAttn(SEQ / 64, NH, NB);
    attn_h_kernel<<<gAttn, 128>>>(qh, kh, vh, att);

    // 4) out-proj + residual(x fp32) -> x1 fp32
    dim3 gProj(EMB / 128, MROWS / 128);
    gemm_h_kernel<float, false, true><<<gProj, 256>>>(
        att, wto, bo, x, x1, MROWS, EMB, EMB);

    // 5) LN2 -> fp16
    ln_kernel<<<MROWS, 256>>>(x1, ln2_g, ln2_b, xn2);

    // 6) FFN1 + ReLU -> fp16 ffn
    dim3 gFF1(FF / 128, MROWS / 128);
    gemm_h_kernel<__half, true, false><<<gFF1, 256>>>(
        xn2, wt1, b1, nullptr, ffn, MROWS, FF, EMB);

    // 7) FFN2 + residual(x1 fp32) -> final fp32 out
    gemm_h_kernel<float, false, true><<<gProj, 256>>>(
        ffn, wt2, b2, x1, out, MROWS, EMB, FF);

    // 8) logits + losses
    loss_kernel<<<1, 128>>>(out, wlr, blr, out + X_SIZE);
}

// round 14
// speedup vs baseline: 11.3028x; 1.1045x over previous
#include <cuda_runtime.h>
#include <cuda_fp16.h>
#include <math.h>
#include <stdint.h>

// Problem dims (fixed by reference)
#define NB 4
#define SEQ 2048
#define EMB 1024
#define NH 16
#define HD 64
#define FF 4096
#define MROWS (NB * SEQ)          // 8192
#define X_SIZE (NB * SEQ * EMB)   // 8388608

// ---------------- scratch (device globals; no allocation allowed) ----------
__device__ __half g_xn [MROWS * EMB];
__device__ __half g_q  [MROWS * EMB];
__device__ __half g_k  [MROWS * EMB];
__device__ __half g_v  [MROWS * EMB];
__device__ __half g_att[MROWS * EMB];
__device__ float  g_x1 [MROWS * EMB];
__device__ __half g_xn2[MROWS * EMB];
__device__ __half g_ffn[MROWS * FF];
// transposed fp16 weights [N][K]
__device__ __half g_wtq[EMB * EMB];
__device__ __half g_wtk[EMB * EMB];
__device__ __half g_wtv[EMB * EMB];
__device__ __half g_wto[EMB * EMB];
__device__ __half g_wt1[FF * EMB];
__device__ __half g_wt2[EMB * FF];

// ---------------- helpers ---------------------------------------------------
__device__ __forceinline__ uint32_t h2u(__half2 h) {
    return *reinterpret_cast<uint32_t*>(&h);
}
__device__ __forceinline__ uint32_t pack_h2(float lo, float hi) {
    return h2u(__floats2half2_rn(lo, hi));
}

__device__ __forceinline__ uint32_t s2u(const void* p) {
    uint32_t a;
    asm("{ .reg .u64 t; cvta.to.shared.u64 t, %1; cvt.u32.u64 %0, t; }"
        : "=r"(a) : "l"(p));
    return a;
}

__device__ __forceinline__ void cp16(uint32_t dst, const void* src) {
    asm volatile("cp.async.cg.shared.global [%0], [%1], 16;"
                 :: "r"(dst), "l"(src));
}
#define CP_COMMIT() asm volatile("cp.async.commit_group;" ::: "memory")
#define CP_WAIT1()  asm volatile("cp.async.wait_group 1;" ::: "memory")

__device__ __forceinline__ void ldm_x4(uint32_t r[4], uint32_t addr) {
    asm volatile("ldmatrix.sync.aligned.m8n8.x4.shared.b16 {%0,%1,%2,%3}, [%4];"
                 : "=r"(r[0]), "=r"(r[1]), "=r"(r[2]), "=r"(r[3])
                 : "r"(addr));
}
__device__ __forceinline__ void ldm_x4_t(uint32_t r[4], uint32_t addr) {
    asm volatile("ldmatrix.sync.aligned.m8n8.x4.trans.shared.b16 {%0,%1,%2,%3}, [%4];"
                 : "=r"(r[0]), "=r"(r[1]), "=r"(r[2]), "=r"(r[3])
                 : "r"(addr));
}

__device__ __forceinline__ void mma_f16(float d[4], const uint32_t a[4],
                                        const uint32_t b0, const uint32_t b1) {
    asm volatile(
        "mma.sync.aligned.m16n8k16.row.col.f32.f16.f16.f32 "
        "{%0,%1,%2,%3},{%4,%5,%6,%7},{%8,%9},{%0,%1,%2,%3};"
        : "+f"(d[0]), "+f"(d[1]), "+f"(d[2]), "+f"(d[3])
        : "r"(a[0]), "r"(a[1]), "r"(a[2]), "r"(a[3]), "r"(b0), "r"(b1));
}

// typed pair-store (fp32 or fp16 destination)
__device__ __forceinline__ void store2(float* p, float a, float b) {
    *reinterpret_cast<float2*>(p) = make_float2(a, b);
}
__device__ __forceinline__ void store2(__half* p, float a, float b) {
    *reinterpret_cast<uint32_t*>(p) = pack_h2(a, b);
}

// ---------------- weight transpose + fp16 convert ---------------------------
__global__ __launch_bounds__(256) void transpose4_h_kernel(
    const float* __restrict__ w0, const float* __restrict__ w1,
    const float* __restrict__ w2, const float* __restrict__ w3,
    __half* __restrict__ o0, __half* __restrict__ o1,
    __half* __restrict__ o2, __half* __restrict__ o3)
{
    const int z = blockIdx.z;
    const float* in = (z == 0) ? w0 : (z == 1) ? w1 : (z == 2) ? w2 : w3;
    __half* out     = (z == 0) ? o0 : (z == 1) ? o1 : (z == 2) ? o2 : o3;
    __shared__ float t[32][33];
    const int bc = blockIdx.x * 32, br = blockIdx.y * 32;
    const int x = threadIdx.x, y0 = threadIdx.y;
#pragma unroll
    for (int y = y0; y < 32; y += 8)
        t[y][x] = in[(size_t)(br + y) * EMB + bc + x];
    __syncthreads();
#pragma unroll
    for (int y = y0; y < 32; y += 8)
        out[(size_t)(bc + y) * EMB + br + x] = __float2half(t[x][y]);
}

__global__ __launch_bounds__(256) void transpose_h_kernel(
    const float* __restrict__ in, __half* __restrict__ out, int R, int C)
{
    __shared__ float t[32][33];
    const int bc = blockIdx.x * 32, br = blockIdx.y * 32;
    const int x = threadIdx.x, y0 = threadIdx.y;
#pragma unroll
    for (int y = y0; y < 32; y += 8)
        t[y][x] = in[(size_t)(br + y) * C + bc + x];
    __syncthreads();
#pragma unroll
    for (int y = y0; y < 32; y += 8)
        out[(size_t)(bc + y) * R + br + x] = __float2half(t[x][y]);
}

// ---------------- layernorm (fp32 in, fp16 out) -----------------------------
__global__ __launch_bounds__(256) void ln_kernel(
    const float* __restrict__ in, const float* __restrict__ g,
    const float* __restrict__ b, __half* __restrict__ out)
{
    const int row = blockIdx.x;
    const float* xr = in + (size_t)row * EMB;
    __half* orow = out + (size_t)row * EMB;
    const int tid = threadIdx.x;

    float vals[4];
    float s = 0.f, sq = 0.f;
#pragma unroll
    for (int i = 0; i < 4; i++) {
        float v = xr[i * 256 + tid];
        vals[i] = v; s += v; sq += v * v;
    }
    __shared__ float red[16];
#pragma unroll
    for (int off = 16; off; off >>= 1) {
        s  += __shfl_xor_sync(0xffffffffu, s,  off);
        sq += __shfl_xor_sync(0xffffffffu, sq, off);
    }
    const int warp = tid >> 5, lane = tid & 31;
    if (lane == 0) { red[warp] = s; red[warp + 8] = sq; }
    __syncthreads();
    if (warp == 0) {
        float ss = (lane < 8) ? red[lane] : 0.f;
        float qq = (lane < 8) ? red[lane + 8] : 0.f;
#pragma unroll
        for (int off = 4; off; off >>= 1) {
            ss += __shfl_xor_sync(0xffffffffu, ss, off);
            qq += __shfl_xor_sync(0xffffffffu, qq, off);
        }
        if (lane == 0) { red[0] = ss; red[1] = qq; }
    }
    __syncthreads();
    const float mean = red[0] * (1.0f / EMB);
    const float var  = red[1] * (1.0f / EMB) - mean * mean;
    const float inv  = rsqrtf(var + 1e-5f);
#pragma unroll
    for (int i = 0; i < 4; i++) {
        int idx = i * 256 + tid;
        orow[idx] = __float2half((vals[i] - mean) * inv * g[idx] + b[idx]);
    }
}

// ---------------- fp16 tensor-core GEMM (cp.async, BK=32, 3-stage) ----------
// C[M,N] = act(A[M,K] @ BT[N,K]^T + bias [+ res]).
// Block tile 128x128, k-step 32, 256 thr (8 warps), warp tile 64x32.
// Smem row pitch 40 halves (80B = 5 x 16B -> conflict-free ldmatrix).
#define PITCH 40
#define STG32 (128 * PITCH)        // halves per stage per operand (5120)
#define STG_BYTES (STG32 * 2)      // bytes per stage per operand (10240)
#define NSTAGE 3
#define GEMM_DSMEM (NSTAGE * STG_BYTES * 2)   // bytes (61440)

template <typename TOut, bool RELU, bool RES>
__device__ __forceinline__ void gemm_h_body(
    const __half* __restrict__ A, const __half* __restrict__ BT,
    const float* __restrict__ bias, const float* __restrict__ res,
    TOut* __restrict__ C, int M, int N, int K, int bx, int by)
{
    extern __shared__ __half dsm[];
    __half* sA = dsm;
    __half* sB = dsm + NSTAGE * STG32;

    const int tid = threadIdx.x;
    const int warpId = tid >> 5, lane = tid & 31;
    const int t = lane & 3, g = lane >> 2;
    const int wr = warpId & 1;
    const int wc = warpId >> 1;
    const int rowStart = by * 128;
    const int colStart = bx * 128;
    const int KT = K / 32;

    // stage-loader mapping: 2 chunks of 16B per operand per thread
    const int r0c = tid >> 2, c0c = (tid & 3) * 8;          // chunk 0
    const int r1c = (tid + 256) >> 2, c1c = ((tid + 256) & 3) * 8;
    const __half* Ap0 = A  + (size_t)(rowStart + r0c) * K + c0c;
    const __half* Ap1 = A  + (size_t)(rowStart + r1c) * K + c1c;
    const __half* Bp0 = BT + (size_t)(colStart + r0c) * K + c0c;
    const __half* Bp1 = BT + (size_t)(colStart + r1c) * K + c1c;
    const uint32_t sA0 = s2u(sA) + (uint32_t)((r0c * PITCH + c0c) * 2);
    const uint32_t sA1 = s2u(sA) + (uint32_t)((r1c * PITCH + c1c) * 2);
    const uint32_t sB0 = s2u(sB) + (uint32_t)((r0c * PITCH + c0c) * 2);
    const uint32_t sB1 = s2u(sB) + (uint32_t)((r1c * PITCH + c1c) * 2);

    // ldmatrix base addresses (per-lane)
    const uint32_t aBase = s2u(sA) +
        (uint32_t)((wr * 64 + (lane & 15)) * (PITCH * 2) + (lane >> 4) * 16);
    const uint32_t bBase = s2u(sB) +
        (uint32_t)((wc * 32 + ((lane >> 4) << 3) + (lane & 7)) * (PITCH * 2) +
                   ((lane >> 3) & 1) * 16);

    float acc[4][4][4];
#pragma unroll
    for (int mt = 0; mt < 4; mt++)
#pragma unroll
        for (int nt = 0; nt < 4; nt++)
#pragma unroll
            for (int r = 0; r < 4; r++) acc[mt][nt][r] = 0.f;

    // prologue: issue stages 0 and 1
#pragma unroll
    for (int st = 0; st < 2; st++) {
        const uint32_t so = st * STG_BYTES;
        cp16(sA0 + so, Ap0 + st * 32);
        cp16(sA1 + so, Ap1 + st * 32);
        cp16(sB0 + so, Bp0 + st * 32);
        cp16(sB1 + so, Bp1 + st * 32);
        CP_COMMIT();
    }

    int buf = 0;
    for (int kt = 0; kt < KT; kt++) {
        CP_WAIT1();            // stage kt landed
        __syncthreads();       // visible to all; also orders prev compute

        // issue stage kt+2 into buffer (kt+2)%3 (compute on it ended iter kt-1)
        if (kt + 2 < KT) {
            const int nb = (buf + 2 >= NSTAGE) ? buf + 2 - NSTAGE : buf + 2;
            const uint32_t so = nb * STG_BYTES;
            const int ko = (kt + 2) * 32;
            cp16(sA0 + so, Ap0 + ko);
            cp16(sA1 + so, Ap1 + ko);
            cp16(sB0 + so, Bp0 + ko);
            cp16(sB1 + so, Bp1 + ko);
        }
        CP_COMMIT();           // keep group count in lockstep

        // ---- compute: two k16 sub-steps on buf ----
        const uint32_t aOff = aBase + buf * STG_BYTES;   // FIXED stride
        const uint32_t bOff = bBase + buf * STG_BYTES;   // FIXED stride
#pragma unroll
        for (int ks = 0; ks < 2; ks++) {
            uint32_t af[4][4];
#pragma unroll
            for (int mt = 0; mt < 4; mt++)
                ldm_x4(af[mt], aOff + ks * 32 + mt * (16 * PITCH * 2));
            uint32_t bf0[4], bf1[4];
            ldm_x4(bf0, bOff + ks * 32);
            ldm_x4(bf1, bOff + ks * 32 + 16 * PITCH * 2);
#pragma unroll
            for (int mt = 0; mt < 4; mt++) {
                mma_f16(acc[mt][0], af[mt], bf0[0], bf0[1]);
                mma_f16(acc[mt][1], af[mt], bf0[2], bf0[3]);
                mma_f16(acc[mt][2], af[mt], bf1[0], bf1[1]);
                mma_f16(acc[mt][3], af[mt], bf1[2], bf1[3]);
            }
        }
        buf = (buf + 1 >= NSTAGE) ? 0 : buf + 1;
    }

    // ---- epilogue ----
#pragma unroll
    for (int mt = 0; mt < 4; mt++) {
        const int r0 = rowStart + wr * 64 + mt * 16 + g;
#pragma unroll
        for (int nt = 0; nt < 4; nt++) {
            const int c0 = colStart + wc * 32 + nt * 8 + t * 2;
            float bx0 = bias[c0], by0 = bias[c0 + 1];
            float v0 = acc[mt][nt][0] + bx0;
            float v1 = acc[mt][nt][1] + by0;
            float v2 = acc[mt][nt][2] + bx0;
            float v3 = acc[mt][nt][3] + by0;
            const size_t off0 = (size_t)r0 * N + c0;
            const size_t off1 = (size_t)(r0 + 8) * N + c0;
            if (RES) {
                float2 q0 = *reinterpret_cast<const float2*>(&res[off0]);
                float2 q1 = *reinterpret_cast<const float2*>(&res[off1]);
                v0 += q0.x; v1 += q0.y; v2 += q1.x; v3 += q1.y;
            }
            if (RELU) {
                v0 = fmaxf(v0, 0.f); v1 = fmaxf(v1, 0.f);
                v2 = fmaxf(v2, 0.f); v3 = fmaxf(v3, 0.f);
            }
            store2(&C[off0], v0, v1);
            store2(&C[off1], v2, v3);
        }
    }
}

template <typename TOut, bool RELU, bool RES>
__global__ __launch_bounds__(256, 2) void gemm_h_kernel(
    const __half* __restrict__ A, const __half* __restrict__ BT,
    const float* __restrict__ bias, const float* __restrict__ res,
    TOut* __restrict__ C, int M, int N, int K)
{
    gemm_h_body<TOut, RELU, RES>(A, BT, bias, res, C, M, N, K,
                                 blockIdx.x, blockIdx.y);
}

__global__ __launch_bounds__(256, 2) void gemm_h_qkv_kernel(
    const __half* __restrict__ A,
    const __half* __restrict__ wt0, const __half* __restrict__ wt1,
    const __half* __restrict__ wt2,
    const float* __restrict__ b0, const float* __restrict__ b1,
    const float* __restrict__ b2,
    __half* __restrict__ c0, __half* __restrict__ c1, __half* __restrict__ c2)
{
    const int z = blockIdx.z;
    const __half* BT  = (z == 0) ? wt0 : (z == 1) ? wt1 : wt2;
    const float* bias = (z == 0) ? b0  : (z == 1) ? b1  : b2;
    __half* C         = (z == 0) ? c0  : (z == 1) ? c1  : c2;
    gemm_h_body<__half, false, false>(A, BT, bias, nullptr, C,
                                      MROWS, EMB, EMB, blockIdx.x, blockIdx.y);
}

// ---------------- flash attention (fp16 m16n8k16) ---------------------------
#define AP 72

__global__ __launch_bounds__(128) void attn_h_kernel(
    const __half* __restrict__ q, const __half* __restrict__ k,
    const __half* __restrict__ v, __half* __restrict__ out)
{
    __shared__ __half Ks[64 * AP];
    __shared__ __half Vs[64 * AP];
    __shared__ __half Ps[64 * AP];

    const int qt = blockIdx.x, h = blockIdx.y, n = blockIdx.z;
    const int tid = threadIdx.x;
    const int warp = tid >> 5, lane = tid & 31;
    const int g = lane >> 2, t = lane & 3;
    const int w16 = warp * 16;
    const size_t base = ((size_t)n * SEQ) * EMB + h * HD;

    const uint32_t ksB = s2u(Ks), vsB = s2u(Vs), psB = s2u(Ps);

#pragma unroll
    for (int it = 0; it < 4; it++) {
        const int u = tid + it * 128;
        const int rr = u >> 3, c8 = (u & 7) * 8;
        *reinterpret_cast<uint4*>(&Ks[rr * AP + c8]) =
            *reinterpret_cast<const uint4*>(
                &q[base + (size_t)(qt * 64 + rr) * EMB + c8]);
    }
    __syncthreads();

    uint32_t qf[4][4];
#pragma unroll
    for (int ks = 0; ks < 4; ks++)
        ldm_x4(qf[ks], ksB + (uint32_t)(((w16 + (lane & 15)) * AP +
                                         ks * 16 + ((lane >> 4) * 8)) * 2));

    float m0 = -INFINITY, m1 = -INFINITY, l0 = 0.f, l1 = 0.f;
    float o[8][4];
#pragma unroll
    for (int nt = 0; nt < 8; nt++)
#pragma unroll
        for (int r = 0; r < 4; r++) o[nt][r] = 0.f;

    for (int kt = 0; kt < SEQ / 64; kt++) {
        __syncthreads();
#pragma unroll
        for (int it = 0; it < 4; it++) {
            const int u = tid + it * 128;
            const int rr = u >> 3, c8 = (u & 7) * 8;
            const size_t gsrc = base + (size_t)(kt * 64 + rr) * EMB + c8;
            *reinterpret_cast<uint4*>(&Ks[rr * AP + c8]) =
                *reinterpret_cast<const uint4*>(&k[gsrc]);
            *reinterpret_cast<uint4*>(&Vs[rr * AP + c8]) =
                *reinterpret_cast<const uint4*>(&v[gsrc]);
        }
        __syncthreads();

        float s[8][4];
#pragma unroll
        for (int nt = 0; nt < 8; nt++)
#pragma unroll
            for (int r = 0; r < 4; r++) s[nt][r] = 0.f;

#pragma unroll
        for (int ks = 0; ks < 4; ks++) {
#pragma unroll
            for (int j = 0; j < 4; j++) {
                uint32_t bf[4];
                ldm_x4(bf, ksB + (uint32_t)(((j * 16 + ((lane >> 4) << 3) +
                                              (lane & 7)) * AP + ks * 16 +
                                             ((lane >> 3) & 1) * 8) * 2));
                mma_f16(s[2 * j],     qf[ks], bf[0], bf[1]);
                mma_f16(s[2 * j + 1], qf[ks], bf[2], bf[3]);
            }
        }

#pragma unroll
        for (int nt = 0; nt < 8; nt++)
#pragma unroll
            for (int r = 0; r < 4; r++) s[nt][r] *= 0.125f;

        float mt0 = -INFINITY, mt1 = -INFINITY;
#pragma unroll
        for (int nt = 0; nt < 8; nt++) {
            mt0 = fmaxf(mt0, fmaxf(s[nt][0], s[nt][1]));
            mt1 = fmaxf(mt1, fmaxf(s[nt][2], s[nt][3]));
        }
        mt0 = fmaxf(mt0, __shfl_xor_sync(0xffffffffu, mt0, 1));
        mt0 = fmaxf(mt0, __shfl_xor_sync(0xffffffffu, mt0, 2));
        mt1 = fmaxf(mt1, __shfl_xor_sync(0xffffffffu, mt1, 1));
        mt1 = fmaxf(mt1, __shfl_xor_sync(0xffffffffu, mt1, 2));

        const float mn0 = fmaxf(m0, mt0), mn1 = fmaxf(m1, mt1);
        const float c0 = __expf(m0 - mn0), c1 = __expf(m1 - mn1);
        float ls0 = 0.f, ls1 = 0.f;
#pragma unroll
        for (int nt = 0; nt < 8; nt++) {
            const float p0 = __expf(s[nt][0] - mn0);
            const float p1 = __expf(s[nt][1] - mn0);
            const float p2 = __expf(s[nt][2] - mn1);
            const float p3 = __expf(s[nt][3] - mn1);
            ls0 += p0 + p1; ls1 += p2 + p3;
            *reinterpret_cast<uint32_t*>(
                &Ps[(w16 + g) * AP + nt * 8 + t * 2]) = pack_h2(p0, p1);
            *reinterpret_cast<uint32_t*>(
                &Ps[(w16 + g + 8) * AP + nt * 8 + t * 2]) = pack_h2(p2, p3);
        }
        ls0 += __shfl_xor_sync(0xffffffffu, ls0, 1);
        ls0 += __shfl_xor_sync(0xffffffffu, ls0, 2);
        ls1 += __shfl_xor_sync(0xffffffffu, ls1, 1);
        ls1 += __shfl_xor_sync(0xffffffffu, ls1, 2);
        l0 = l0 * c0 + ls0; l1 = l1 * c1 + ls1;
        m0 = mn0; m1 = mn1;
#pragma unroll
        for (int nt = 0; nt < 8; nt++) {
            o[nt][0] *= c0; o[nt][1] *= c0;
            o[nt][2] *= c1; o[nt][3] *= c1;
        }
        __syncwarp();

#pragma unroll
        for (int ks = 0; ks < 4; ks++) {
            uint32_t pf[4];
            ldm_x4(pf, psB + (uint32_t)(((w16 + (lane & 15)) * AP + ks * 16 +
                                         ((lane >> 4) * 8)) * 2));
#pragma unroll
            for (int j = 0; j < 4; j++) {
                uint32_t vf[4];
                const int row = ks * 16 + (lane & 7) + ((lane >> 3) & 1) * 8;
                ldm_x4_t(vf, vsB + (uint32_t)((row * AP + j * 16 +
                                               (lane >> 4) * 8) * 2));
                mma_f16(o[2 * j],     pf, vf[0], vf[1]);
                mma_f16(o[2 * j + 1], pf, vf[2], vf[3]);
            }
        }
    }

    const float i0 = 1.f / l0, i1 = 1.f / l1;
    const size_t row0 = base + (size_t)(qt * 64 + w16 + g) * EMB;
    const size_t row1 = base + (size_t)(qt * 64 + w16 + g + 8) * EMB;
#pragma unroll
    for (int nt = 0; nt < 8; nt++) {
        const int c = nt * 8 + t * 2;
        *reinterpret_cast<uint32_t*>(&out[row0 + c]) =
            pack_h2(o[nt][0] * i0, o[nt][1] * i0);
        *reinterpret_cast<uint32_t*>(&out[row1 + c]) =
            pack_h2(o[nt][2] * i1, o[nt][3] * i1);
    }
}

// ---------------- logits + GAN loss -----------------------------------------
__global__ void loss_kernel(const float* __restrict__ xfin,
                            const float* __restrict__ wlr,
                            const float* __restrict__ blr,
                            float* __restrict__ out)
{
    __shared__ float slog[4];
    const int warp = threadIdx.x >> 5, lane = threadIdx.x & 31;
    if (warp < 4) {
        const float* xr = xfin + (size_t)warp * SEQ * EMB;  // token 0
        float s = 0.f;
        for (int i = lane; i < EMB; i += 32) s = fmaf(xr[i], wlr[i], s);
#pragma unroll
        for (int off = 16; off; off >>= 1)
            s += __shfl_xor_sync(0xffffffffu, s, off);
        if (lane == 0) slog[warp] = s + blr[0];
    }
    __syncthreads();
    if (threadIdx.x == 0) {
        auto sp = [](float t) {
            return fmaxf(t, 0.f) + log1pf(expf(-fabsf(t)));
        };
        float loss_real = 0.5f * (sp(-slog[0]) + sp(-slog[1]));
        float loss_fake = 0.5f * (sp( slog[2]) + sp( slog[3]));
        out[0] = 0.5f * (loss_fake + loss_real);
        out[1] = loss_fake;
    }
}

// ---------------- launch ----------------------------------------------------
extern "C" void kernel_launch(void* const* d_in, const int* in_sizes, int n_in,
                              void* d_out, int out_size)
{
    const float* x     = (const float*)d_in[0];
    const float* wq    = (const float*)d_in[1];
    const float* bq    = (const float*)d_in[2];
    const float* wk    = (const float*)d_in[3];
    const float* bk    = (const float*)d_in[4];
    const float* wv    = (const float*)d_in[5];
    const float* bv    = (const float*)d_in[6];
    const float* wo    = (const float*)d_in[7];
    const float* bo    = (const float*)d_in[8];
    const float* ln1_g = (const float*)d_in[9];
    const float* ln1_b = (const float*)d_in[10];
    const float* ln2_g = (const float*)d_in[11];
    const float* ln2_b = (const float*)d_in[12];
    const float* w1    = (const float*)d_in[13];
    const float* b1    = (const float*)d_in[14];
    const float* w2    = (const float*)d_in[15];
    const float* b2    = (const float*)d_in[16];
    const float* wlr   = (const float*)d_in[17];
    const float* blr   = (const float*)d_in[18];
    float* out = (float*)d_out;

    __half *xn, *qh, *kh, *vh, *att, *xn2, *ffn;
    float* x1;
    __half *wtq, *wtk, *wtv, *wto, *wt1, *wt2;
    cudaGetSymbolAddress((void**)&xn,  g_xn);
    cudaGetSymbolAddress((void**)&qh,  g_q);
    cudaGetSymbolAddress((void**)&kh,  g_k);
    cudaGetSymbolAddress((void**)&vh,  g_v);
    cudaGetSymbolAddress((void**)&att, g_att);
    cudaGetSymbolAddress((void**)&x1,  g_x1);
    cudaGetSymbolAddress((void**)&xn2, g_xn2);
    cudaGetSymbolAddress((void**)&ffn, g_ffn);
    cudaGetSymbolAddress((void**)&wtq, g_wtq);
    cudaGetSymbolAddress((void**)&wtk, g_wtk);
    cudaGetSymbolAddress((void**)&wtv, g_wtv);
    cudaGetSymbolAddress((void**)&wto, g_wto);
    cudaGetSymbolAddress((void**)&wt1, g_wt1);
    cudaGetSymbolAddress((void**)&wt2, g_wt2);

    // raise dynamic smem limits
    cudaFuncSetAttribute(gemm_h_kernel<float, false, true>,
                         cudaFuncAttributeMaxDynamicSharedMemorySize, GEMM_DSMEM);
    cudaFuncSetAttribute(gemm_h_kernel<__half, true, false>,
                         cudaFuncAttributeMaxDynamicSharedMemorySize, GEMM_DSMEM);
    cudaFuncSetAttribute(gemm_h_qkv_kernel,
                         cudaFuncAttributeMaxDynamicSharedMemorySize, GEMM_DSMEM);

    // 0) weight transposes + fp16 convert
    dim3 tb(32, 8);
    transpose4_h_kernel<<<dim3(EMB / 32, EMB / 32, 4), tb>>>(
        wq, wk, wv, wo, wtq, wtk, wtv, wto);
    transpose_h_kernel<<<dim3(FF / 32,  EMB / 32), tb>>>(w1, wt1, EMB, FF);
    transpose_h_kernel<<<dim3(EMB / 32, FF / 32),  tb>>>(w2, wt2, FF, EMB);

    // 1) LN1 -> fp16
    ln_kernel<<<MROWS, 256>>>(x, ln1_g, ln1_b, xn);

    // 2) QKV projections -> fp16 q,k,v
    dim3 gQKV(EMB / 128, MROWS / 128, 3);
    gemm_h_qkv_kernel<<<gQKV, 256, GEMM_DSMEM>>>(xn, wtq, wtk, wtv,
                                                 bq, bk, bv, qh, kh, vh);

    // 3) attention (fp16 mma) -> fp16 att
    dim3 gAttn(SEQ / 64, NH, NB);
    attn_h_kernel<<<gAttn, 128>>>(qh, kh, vh, att);

    // 4) out-proj + residual(x fp32) -> x1 fp32
    dim3 gProj(EMB / 128, MROWS / 128);
    gemm_h_kernel<float, false, true><<<gProj, 256, GEMM_DSMEM>>>(
        att, wto, bo, x, x1, MROWS, EMB, EMB);

    // 5) LN2 -> fp16
    ln_kernel<<<MROWS, 256>>>(x1, ln2_g, ln2_b, xn2);

    // 6) FFN1 + ReLU -> fp16 ffn
    dim3 gFF1(FF / 128, MROWS / 128);
    gemm_h_kernel<__half, true, false><<<gFF1, 256, GEMM_DSMEM>>>(
        xn2, wt1, b1, nullptr, ffn, MROWS, FF, EMB);

    // 7) FFN2 + residual(x1 fp32) -> final fp32 out
    gemm_h_kernel<float, false, true><<<gProj, 256, GEMM_DSMEM>>>(
        ffn, wt2, b2, x1, out, MROWS, EMB, FF);

    // 8) logits + losses
    loss_kernel<<<1, 128>>>(out, wlr, blr, out + X_SIZE);
}